// round 11
// baseline (speedup 1.0000x reference)
#include <cuda_runtime.h>
#include <cuda_bf16.h>
#include <cstdint>

#define NN 50000
#define EE 800000
#define CC 128
#define NEG 0.01f

// Scratch (no allocation allowed -> __device__ globals)
__device__ float g_y[NN * CC];
__device__ float g_t[NN * CC];
__device__ float g_aggr[NN * CC];
__device__ float g_delta[NN * 3];
__device__ int   g_is64;
// Fragment-major weights: per matrix 4096 x uint4 {bhi0,bhi1,blo0,blo1} = 64KB
// index (per matrix): ct*256 + kc*32 + g*4 + q
__device__ uint4 g_fragW[4 * 4096];

__device__ __forceinline__ float leaky(float v) {
    return v >= 0.0f ? v : NEG * v;
}

// ---------------------------------------------------------------------------
__global__ void detect_dtype_kernel(const int* __restrict__ ei32, int n_words)
{
    if (blockIdx.x == 0 && threadIdx.x == 0) {
        int all_hi_zero = 1;
        int pairs = n_words / 2;
        if (pairs > 1024) pairs = 1024;
        for (int p = 0; p < pairs; ++p) {
            if (ei32[2 * p + 1] != 0) { all_hi_zero = 0; break; }
        }
        g_is64 = all_hi_zero;
    }
}

// ---------------------------------------------------------------------------
__device__ __forceinline__ uint32_t pack_hi(float a, float b) {
    __nv_bfloat16 ha = __float2bfloat16(a), hb = __float2bfloat16(b);
    return (uint32_t)__bfloat16_as_ushort(ha) | ((uint32_t)__bfloat16_as_ushort(hb) << 16);
}
__device__ __forceinline__ uint32_t pack_lo(float a, float b) {
    __nv_bfloat16 ha = __float2bfloat16(a), hb = __float2bfloat16(b);
    __nv_bfloat16 la = __float2bfloat16(a - __bfloat162float(ha));
    __nv_bfloat16 lb = __float2bfloat16(b - __bfloat162float(hb));
    return (uint32_t)__bfloat16_as_ushort(la) | ((uint32_t)__bfloat16_as_ushort(lb) << 16);
}

__global__ void prep_weights_kernel(const float* __restrict__ w0,
                                    const float* __restrict__ w1,
                                    const float* __restrict__ w2,
                                    const float* __restrict__ w3)
{
    int idx = blockIdx.x * 256 + threadIdx.x;   // 4*4096 entries
    if (idx >= 4 * 4096) return;
    int m = idx >> 12;
    int rem = idx & 4095;
    int col = rem >> 5;        // 0..127
    int kc  = (rem >> 2) & 7;  // 0..7
    int q   = rem & 3;         // 0..3
    const float* w = (m == 0) ? w0 : (m == 1) ? w1 : (m == 2) ? w2 : w3;
    int k0 = kc * 16 + 2 * q;
    float a0 = w[(k0 + 0) * CC + col];
    float a1 = w[(k0 + 1) * CC + col];
    float a2 = w[(k0 + 8) * CC + col];
    float a3 = w[(k0 + 9) * CC + col];
    uint4 v;
    v.x = pack_hi(a0, a1);
    v.y = pack_hi(a2, a3);
    v.z = pack_lo(a0, a1);
    v.w = pack_lo(a2, a3);
    int ct = col >> 3, g = col & 7;
    g_fragW[m * 4096 + ct * 256 + kc * 32 + g * 4 + q] = v;
}

// ---------------------------------------------------------------------------
__device__ __forceinline__ void mma_bf16(float* c, const uint32_t* a, const uint32_t* b)
{
    asm volatile(
        "mma.sync.aligned.m16n8k16.row.col.f32.bf16.bf16.f32 "
        "{%0,%1,%2,%3}, {%4,%5,%6,%7}, {%8,%9}, {%0,%1,%2,%3};"
        : "+f"(c[0]), "+f"(c[1]), "+f"(c[2]), "+f"(c[3])
        : "r"(a[0]), "r"(a[1]), "r"(a[2]), "r"(a[3]), "r"(b[0]), "r"(b[1]));
}

// ---------------------------------------------------------------------------
// Split-bf16 GEMM, 512 threads / 16 warps, warp tile 16x64.
// A converted fp32 -> interleaved {hi,lo} u32 pairs DURING STAGING:
//   smem u32 index = row*72 + 2p (+1 for lo), pair p = k/2 within the half.
// Inner loop: 4x LDS.64 (A hi+lo) + 8x LDS.128 (W) + 24 MMA, zero conversion.
// 2 CTAs/SM. act: 0 none(+resid), 1 leaky, 2 delta-fused.
// smem: A [0, 36864); W [36864, 102400); bias [102400,+512); hw2 [102912,+1536)
// ---------------------------------------------------------------------------
#define SM_W    36864
#define SM_BIAS 102400
#define SM_HW2  102912
#define SM_TOT  104448

__global__ __launch_bounds__(512, 2) void gemm_mma(
    const float* __restrict__ A, const uint4* __restrict__ fragW,
    const float* __restrict__ bias, const float* __restrict__ resid,
    float* __restrict__ out, int M, int act,
    const float* __restrict__ hw2, const float* __restrict__ hb2,
    float* __restrict__ delta)
{
    extern __shared__ char sm[];
    uint32_t* sA = (uint32_t*)sm;                 // [128][72] u32 (hi/lo pairs)
    uint4* sW = (uint4*)(sm + SM_W);              // 4096 uint4
    const int tid = threadIdx.x;

    // Copy W (fragment-major, verbatim) + bias (+ hw2 in delta mode)
#pragma unroll
    for (int i = 0; i < 8; i++)
        sW[tid + i * 512] = fragW[tid + i * 512];
    if (tid < 128) ((float*)(sm + SM_BIAS))[tid] = bias[tid];
    if (act == 2) {
        for (int i = tid; i < 384; i += 512)
            ((float*)(sm + SM_HW2))[i] = hw2[i];
    }

    const int warp = tid >> 5, lane = tid & 31;
    const int g = lane >> 2, q = lane & 3;
    const int warp_m = warp >> 1, warp_n = warp & 1;
    const int r0 = warp_m * 16;

    float acc[8][4];
#pragma unroll
    for (int ct = 0; ct < 8; ct++)
#pragma unroll
        for (int c = 0; c < 4; c++) acc[ct][c] = 0.f;

    const int srow = tid & 127;
    const int sseg = (tid >> 7) * 4;          // float4 seg base 0,4,8,12
    const int grow = blockIdx.x * 128 + srow;
    const uint32_t* a0base = sA + (r0 + g) * 72;
    const uint32_t* a1base = sA + (r0 + g + 8) * 72;

    for (int half = 0; half < 2; half++) {
        // Stage A chunk [128 rows x 64 cols] with fp32->bf16 hi/lo conversion.
        // float4 seg s covers pairs 2s, 2s+1 -> u32 idx 4s..4s+3 =
        // {hi_2s, lo_2s, hi_2s+1, lo_2s+1}, one STS.128 per seg.
        {
            const float4* src = (grow < M)
                ? (const float4*)(A + (size_t)grow * CC + half * 64) : nullptr;
            uint32_t* dst = sA + srow * 72;
#pragma unroll
            for (int i = 0; i < 4; i++) {
                float4 v = src ? src[sseg + i] : make_float4(0.f, 0.f, 0.f, 0.f);
                uint4 pk;
                pk.x = pack_hi(v.x, v.y);
                pk.y = pack_lo(v.x, v.y);
                pk.z = pack_hi(v.z, v.w);
                pk.w = pack_lo(v.z, v.w);
                *(uint4*)(dst + (sseg + i) * 4) = pk;
            }
        }
        __syncthreads();

#pragma unroll
        for (int kc2 = 0; kc2 < 4; kc2++) {
            const int kc = half * 4 + kc2;
            const int p0 = kc2 * 8 + q;       // pair index within half
            uint2 u00 = *(const uint2*)(a0base + 2 * p0);       // {ahi0, alo0}
            uint2 u10 = *(const uint2*)(a1base + 2 * p0);       // {ahi1, alo1}
            uint2 u01 = *(const uint2*)(a0base + 2 * p0 + 8);   // {ahi2, alo2}
            uint2 u11 = *(const uint2*)(a1base + 2 * p0 + 8);   // {ahi3, alo3}
            uint32_t ahi[4] = { u00.x, u10.x, u01.x, u11.x };
            uint32_t alo[4] = { u00.y, u10.y, u01.y, u11.y };

            const uint4* wbase = sW + kc * 32 + g * 4 + q;
#pragma unroll
            for (int ct = 0; ct < 8; ct++) {
                uint4 wv = wbase[(warp_n * 8 + ct) * 256];
                uint32_t bh[2] = { wv.x, wv.y };
                uint32_t bl[2] = { wv.z, wv.w };
                mma_bf16(acc[ct], ahi, bh);
                mma_bf16(acc[ct], ahi, bl);
                mma_bf16(acc[ct], alo, bh);
            }
        }
        __syncthreads();
    }

    const float* sbias = (const float*)(sm + SM_BIAS);
    int orow0 = blockIdx.x * 128 + r0 + g;
    int orow1 = orow0 + 8;

    if (act == 2) {
        // delta: leaky(acc+bias) @ hw2, quad-reduce, cross-warp_n sum via smem
        const float* shw2 = (const float*)(sm + SM_HW2);
        float* sPart = (float*)(sm + SM_W);   // [2][128][3] floats (W dead)
        float p0[3] = {0.f, 0.f, 0.f}, p1[3] = {0.f, 0.f, 0.f};
#pragma unroll
        for (int ct = 0; ct < 8; ct++) {
            int col = (warp_n * 8 + ct) * 8 + q * 2;
            float b0 = sbias[col], b1 = sbias[col + 1];
            float v00 = leaky(acc[ct][0] + b0), v01 = leaky(acc[ct][1] + b1);
            float v10 = leaky(acc[ct][2] + b0), v11 = leaky(acc[ct][3] + b1);
#pragma unroll
            for (int d = 0; d < 3; d++) {
                p0[d] += v00 * shw2[col * 3 + d] + v01 * shw2[(col + 1) * 3 + d];
                p1[d] += v10 * shw2[col * 3 + d] + v11 * shw2[(col + 1) * 3 + d];
            }
        }
#pragma unroll
        for (int d = 0; d < 3; d++) {
            p0[d] += __shfl_xor_sync(0xFFFFFFFFu, p0[d], 1);
            p0[d] += __shfl_xor_sync(0xFFFFFFFFu, p0[d], 2);
            p1[d] += __shfl_xor_sync(0xFFFFFFFFu, p1[d], 1);
            p1[d] += __shfl_xor_sync(0xFFFFFFFFu, p1[d], 2);
        }
        if (q == 0) {
            int row0 = r0 + g, row1 = row0 + 8;
#pragma unroll
            for (int d = 0; d < 3; d++) {
                sPart[(warp_n * 128 + row0) * 3 + d] = p0[d];
                sPart[(warp_n * 128 + row1) * 3 + d] = p1[d];
            }
        }
        __syncthreads();
        if (tid < 128) {
            int orow = blockIdx.x * 128 + tid;
            if (orow < M) {
#pragma unroll
                for (int d = 0; d < 3; d++)
                    delta[orow * 3 + d] = tanhf(sPart[tid * 3 + d] +
                                                sPart[(128 + tid) * 3 + d] + hb2[d]);
            }
        }
        return;
    }

#pragma unroll
    for (int ct = 0; ct < 8; ct++) {
        int col = (warp_n * 8 + ct) * 8 + q * 2;
        float b0 = sbias[col], b1 = sbias[col + 1];
        float v00 = acc[ct][0] + b0, v01 = acc[ct][1] + b1;
        float v10 = acc[ct][2] + b0, v11 = acc[ct][3] + b1;
        if (act == 1) {
            v00 = leaky(v00); v01 = leaky(v01);
            v10 = leaky(v10); v11 = leaky(v11);
        }
        if (orow0 < M) {
            if (resid) {
                float2 r = *(const float2*)(resid + (size_t)orow0 * CC + col);
                v00 += r.x; v01 += r.y;
            }
            *(float2*)(out + (size_t)orow0 * CC + col) = make_float2(v00, v01);
        }
        if (orow1 < M) {
            if (resid) {
                float2 r = *(const float2*)(resid + (size_t)orow1 * CC + col);
                v10 += r.x; v11 += r.y;
            }
            *(float2*)(out + (size_t)orow1 * CC + col) = make_float2(v10, v11);
        }
    }
}

// ---------------------------------------------------------------------------
// Edge kernel: one warp per edge; scatter-add via red.global.add.v4.f32
// ---------------------------------------------------------------------------
__global__ __launch_bounds__(256) void edge_kernel(
    const void* __restrict__ ei_raw, const float* __restrict__ pos,
    const float* __restrict__ delta, const float* __restrict__ y,
    const float* __restrict__ f_w, float* __restrict__ aggr, int E, int M)
{
    int e = (blockIdx.x * 256 + threadIdx.x) >> 5;
    int lane = threadIdx.x & 31;
    if (e >= E) return;

    int j, i;
    if (g_is64) {
        const long long* ei = (const long long*)ei_raw;
        j = (int)ei[e];
        i = (int)ei[E + e];
    } else {
        const int* ei = (const int*)ei_raw;
        j = ei[e];
        i = ei[E + e];
    }
    if ((unsigned)j >= (unsigned)M || (unsigned)i >= (unsigned)M) return;

    float r0 = pos[j * 3 + 0] - pos[i * 3 + 0] + delta[i * 3 + 0];
    float r1 = pos[j * 3 + 1] - pos[i * 3 + 1] + delta[i * 3 + 1];
    float r2 = pos[j * 3 + 2] - pos[i * 3 + 2] + delta[i * 3 + 2];

    int c = lane * 4;
    float4 yv = *(const float4*)(y + (size_t)j * CC + c);
    float4 w0 = *(const float4*)(f_w + 0 * CC + c);
    float4 w1 = *(const float4*)(f_w + 1 * CC + c);
    float4 w2 = *(const float4*)(f_w + 2 * CC + c);

    float4 z;
    z.x = leaky(yv.x + r0 * w0.x + r1 * w1.x + r2 * w2.x);
    z.y = leaky(yv.y + r0 * w0.y + r1 * w1.y + r2 * w2.y);
    z.z = leaky(yv.z + r0 * w0.z + r1 * w1.z + r2 * w2.z);
    z.w = leaky(yv.w + r0 * w0.w + r1 * w1.w + r2 * w2.w);

    float* dst = aggr + (size_t)i * CC + c;
    asm volatile("red.global.add.v4.f32 [%0], {%1,%2,%3,%4};"
                 :: "l"(dst), "f"(z.x), "f"(z.y), "f"(z.z), "f"(z.w)
                 : "memory");
}

// ---------------------------------------------------------------------------
extern "C" void kernel_launch(void* const* d_in, const int* in_sizes, int n_in,
                              void* d_out, int out_size)
{
    const float* x      = (const float*)d_in[0];
    const float* pos    = (const float*)d_in[1];
    const void*  ei     = d_in[2];
    const float* h_w1   = (const float*)d_in[3];
    const float* h_b1   = (const float*)d_in[4];
    const float* h_w2   = (const float*)d_in[5];
    const float* h_b2   = (const float*)d_in[6];
    const float* f_w    = (const float*)d_in[7];
    const float* f_b    = (const float*)d_in[8];
    const float* g_w1   = (const float*)d_in[9];
    const float* g_b1   = (const float*)d_in[10];
    const float* g_w2   = (const float*)d_in[11];
    const float* g_b2   = (const float*)d_in[12];
    float* out = (float*)d_out;

    const int M = in_sizes[0] / CC;  // 50000
    const int E = in_sizes[2] / 2;   // 800000

    float *y, *t, *aggr, *delta;
    uint4* fragW;
    cudaGetSymbolAddress((void**)&y,     g_y);
    cudaGetSymbolAddress((void**)&t,     g_t);
    cudaGetSymbolAddress((void**)&aggr,  g_aggr);
    cudaGetSymbolAddress((void**)&delta, g_delta);
    cudaGetSymbolAddress((void**)&fragW, g_fragW);

    static int smem_set = 0;
    if (!smem_set) {
        cudaFuncSetAttribute(gemm_mma, cudaFuncAttributeMaxDynamicSharedMemorySize, SM_TOT);
        smem_set = 1;
    }

    const int gcta = (M + 127) / 128;

    // --- prep ---
    detect_dtype_kernel<<<1, 32>>>((const int*)ei, 2048);
    prep_weights_kernel<<<(4 * 4096 + 255) / 256, 256>>>(h_w1, f_w + 3 * CC, g_w1, g_w2);
    cudaMemsetAsync(aggr, 0, (size_t)M * CC * sizeof(float));

    // --- GEMMs + delta ---
    // delta = tanh(leaky(x @ h_w1 + h_b1) @ h_w2 + h_b2)  (fused, hidden never stored)
    gemm_mma<<<gcta, 512, SM_TOT>>>(x, fragW + 0 * 4096, h_b1, nullptr, nullptr, M, 2,
                                    h_w2, h_b2, delta);
    // y = x @ f_w[3:, :] + f_b
    gemm_mma<<<gcta, 512, SM_TOT>>>(x, fragW + 1 * 4096, f_b, nullptr, y, M, 0,
                                    nullptr, nullptr, nullptr);

    // --- aggregation via atomics ---
    edge_kernel<<<(E + 7) / 8, 256>>>(ei, pos, delta, y, f_w, aggr, E, M);

    // t = leaky(aggr @ g_w1 + g_b1)
    gemm_mma<<<gcta, 512, SM_TOT>>>(aggr, fragW + 2 * 4096, g_b1, nullptr, t, M, 1,
                                    nullptr, nullptr, nullptr);
    // out = t @ g_w2 + g_b2 + x
    gemm_mma<<<gcta, 512, SM_TOT>>>(t, fragW + 3 * 4096, g_b2, x, out, M, 0,
                                    nullptr, nullptr, nullptr);
}

// round 12
// speedup vs baseline: 1.2320x; 1.2320x over previous
#include <cuda_runtime.h>
#include <cuda_bf16.h>
#include <cstdint>

#define NN 50000
#define EE 800000
#define CC 128
#define NEG 0.01f

// Scratch (no allocation allowed -> __device__ globals)
__device__ float g_y[NN * CC];
__device__ float g_t[NN * CC];
__device__ float g_aggr[NN * CC];
__device__ float g_delta[NN * 3];
__device__ int   g_is64;
// CSR scratch
__device__ int g_deg[NN];
__device__ int g_off[NN];
__device__ int g_cur[NN];
__device__ int g_ssrc[EE];
__device__ int g_bsum[256];
// Fragment-major weights: per matrix 4096 x uint4 {bhi0,bhi1,blo0,blo1} = 64KB
// index (per matrix): ct*256 + kc*32 + g*4 + q
__device__ uint4 g_fragW[4 * 4096];

__device__ __forceinline__ float leaky(float v) {
    return v >= 0.0f ? v : NEG * v;
}

// ---------------------------------------------------------------------------
__global__ void detect_dtype_kernel(const int* __restrict__ ei32, int n_words)
{
    if (blockIdx.x == 0 && threadIdx.x == 0) {
        int all_hi_zero = 1;
        int pairs = n_words / 2;
        if (pairs > 1024) pairs = 1024;
        for (int p = 0; p < pairs; ++p) {
            if (ei32[2 * p + 1] != 0) { all_hi_zero = 0; break; }
        }
        g_is64 = all_hi_zero;
    }
}

// ---------------------------------------------------------------------------
__device__ __forceinline__ uint32_t pack_hi(float a, float b) {
    __nv_bfloat16 ha = __float2bfloat16(a), hb = __float2bfloat16(b);
    return (uint32_t)__bfloat16_as_ushort(ha) | ((uint32_t)__bfloat16_as_ushort(hb) << 16);
}
__device__ __forceinline__ uint32_t pack_lo(float a, float b) {
    __nv_bfloat16 ha = __float2bfloat16(a), hb = __float2bfloat16(b);
    __nv_bfloat16 la = __float2bfloat16(a - __bfloat162float(ha));
    __nv_bfloat16 lb = __float2bfloat16(b - __bfloat162float(hb));
    return (uint32_t)__bfloat16_as_ushort(la) | ((uint32_t)__bfloat16_as_ushort(lb) << 16);
}

__global__ void prep_weights_kernel(const float* __restrict__ w0,
                                    const float* __restrict__ w1,
                                    const float* __restrict__ w2,
                                    const float* __restrict__ w3)
{
    int idx = blockIdx.x * 256 + threadIdx.x;   // 4*4096 entries
    if (idx >= 4 * 4096) return;
    int m = idx >> 12;
    int rem = idx & 4095;
    int col = rem >> 5;        // 0..127
    int kc  = (rem >> 2) & 7;  // 0..7
    int q   = rem & 3;         // 0..3
    const float* w = (m == 0) ? w0 : (m == 1) ? w1 : (m == 2) ? w2 : w3;
    int k0 = kc * 16 + 2 * q;
    float a0 = w[(k0 + 0) * CC + col];
    float a1 = w[(k0 + 1) * CC + col];
    float a2 = w[(k0 + 8) * CC + col];
    float a3 = w[(k0 + 9) * CC + col];
    uint4 v;
    v.x = pack_hi(a0, a1);
    v.y = pack_hi(a2, a3);
    v.z = pack_lo(a0, a1);
    v.w = pack_lo(a2, a3);
    int ct = col >> 3, g = col & 7;
    g_fragW[m * 4096 + ct * 256 + kc * 32 + g * 4 + q] = v;
}

// ---------------------------------------------------------------------------
__device__ __forceinline__ void mma_bf16(float* c, const uint32_t* a, const uint32_t* b)
{
    asm volatile(
        "mma.sync.aligned.m16n8k16.row.col.f32.bf16.bf16.f32 "
        "{%0,%1,%2,%3}, {%4,%5,%6,%7}, {%8,%9}, {%0,%1,%2,%3};"
        : "+f"(c[0]), "+f"(c[1]), "+f"(c[2]), "+f"(c[3])
        : "r"(a[0]), "r"(a[1]), "r"(a[2]), "r"(a[3]), "r"(b[0]), "r"(b[1]));
}

__device__ __forceinline__ void cvt_hilo(float2 f, uint32_t& hi, uint32_t& lo)
{
    __nv_bfloat16 hx = __float2bfloat16(f.x);
    __nv_bfloat16 hy = __float2bfloat16(f.y);
    __nv_bfloat16 lx = __float2bfloat16(f.x - __bfloat162float(hx));
    __nv_bfloat16 ly = __float2bfloat16(f.y - __bfloat162float(hy));
    hi = (uint32_t)__bfloat16_as_ushort(hx) | ((uint32_t)__bfloat16_as_ushort(hy) << 16);
    lo = (uint32_t)__bfloat16_as_ushort(lx) | ((uint32_t)__bfloat16_as_ushort(ly) << 16);
}

// ---------------------------------------------------------------------------
// Split-bf16 GEMM (R10, proven): 512 threads / 16 warps, warp tile 16x64.
// W in smem fragment-major; A staged fp32 in 2 K-chunks of 64 cols (stride 72).
// 2 CTAs/SM. act: 0 none(+resid), 1 leaky, 2 delta-fused.
// smem: A [0, 36864); W [36864, 102400); bias [102400,+512); hw2 [102912,+1536)
// ---------------------------------------------------------------------------
#define SM_W    36864
#define SM_BIAS 102400
#define SM_HW2  102912
#define SM_TOT  104448

__global__ __launch_bounds__(512, 2) void gemm_mma(
    const float* __restrict__ A, const uint4* __restrict__ fragW,
    const float* __restrict__ bias, const float* __restrict__ resid,
    float* __restrict__ out, int M, int act,
    const float* __restrict__ hw2, const float* __restrict__ hb2,
    float* __restrict__ delta)
{
    extern __shared__ char sm[];
    float* sA = (float*)sm;                       // [128][72]
    uint4* sW = (uint4*)(sm + SM_W);              // 4096 uint4
    const int tid = threadIdx.x;

#pragma unroll
    for (int i = 0; i < 8; i++)
        sW[tid + i * 512] = fragW[tid + i * 512];
    if (tid < 128) ((float*)(sm + SM_BIAS))[tid] = bias[tid];
    if (act == 2) {
        for (int i = tid; i < 384; i += 512)
            ((float*)(sm + SM_HW2))[i] = hw2[i];
    }

    const int warp = tid >> 5, lane = tid & 31;
    const int g = lane >> 2, q = lane & 3;
    const int warp_m = warp >> 1, warp_n = warp & 1;
    const int r0 = warp_m * 16;

    float acc[8][4];
#pragma unroll
    for (int ct = 0; ct < 8; ct++)
#pragma unroll
        for (int c = 0; c < 4; c++) acc[ct][c] = 0.f;

    const int srow = tid & 127;
    const int sseg = (tid >> 7) * 4;          // float4 seg base 0,4,8,12
    const int grow = blockIdx.x * 128 + srow;
    const float* a0base = sA + (r0 + g) * 72;
    const float* a1base = sA + (r0 + g + 8) * 72;

    for (int half = 0; half < 2; half++) {
        {
            const float4* src = (grow < M)
                ? (const float4*)(A + (size_t)grow * CC + half * 64) : nullptr;
            float* dst = sA + srow * 72;
#pragma unroll
            for (int i = 0; i < 4; i++) {
                float4 v = src ? src[sseg + i] : make_float4(0.f, 0.f, 0.f, 0.f);
                *(float4*)(dst + (sseg + i) * 4) = v;
            }
        }
        __syncthreads();

#pragma unroll
        for (int kc2 = 0; kc2 < 4; kc2++) {
            const int kc = half * 4 + kc2;
            const int k0 = kc2 * 16 + q * 2;
            float2 f00 = *(const float2*)(a0base + k0);
            float2 f10 = *(const float2*)(a1base + k0);
            float2 f01 = *(const float2*)(a0base + k0 + 8);
            float2 f11 = *(const float2*)(a1base + k0 + 8);
            uint32_t ahi[4], alo[4];
            cvt_hilo(f00, ahi[0], alo[0]);
            cvt_hilo(f10, ahi[1], alo[1]);
            cvt_hilo(f01, ahi[2], alo[2]);
            cvt_hilo(f11, ahi[3], alo[3]);

            const uint4* wbase = sW + kc * 32 + g * 4 + q;
#pragma unroll
            for (int ct = 0; ct < 8; ct++) {
                uint4 wv = wbase[(warp_n * 8 + ct) * 256];
                uint32_t bh[2] = { wv.x, wv.y };
                uint32_t bl[2] = { wv.z, wv.w };
                mma_bf16(acc[ct], ahi, bh);
                mma_bf16(acc[ct], ahi, bl);
                mma_bf16(acc[ct], alo, bh);
            }
        }
        __syncthreads();
    }

    const float* sbias = (const float*)(sm + SM_BIAS);
    int orow0 = blockIdx.x * 128 + r0 + g;
    int orow1 = orow0 + 8;

    if (act == 2) {
        const float* shw2 = (const float*)(sm + SM_HW2);
        float* sPart = (float*)(sm + SM_W);   // [2][128][3] floats (W dead)
        float p0[3] = {0.f, 0.f, 0.f}, p1[3] = {0.f, 0.f, 0.f};
#pragma unroll
        for (int ct = 0; ct < 8; ct++) {
            int col = (warp_n * 8 + ct) * 8 + q * 2;
            float b0 = sbias[col], b1 = sbias[col + 1];
            float v00 = leaky(acc[ct][0] + b0), v01 = leaky(acc[ct][1] + b1);
            float v10 = leaky(acc[ct][2] + b0), v11 = leaky(acc[ct][3] + b1);
#pragma unroll
            for (int d = 0; d < 3; d++) {
                p0[d] += v00 * shw2[col * 3 + d] + v01 * shw2[(col + 1) * 3 + d];
                p1[d] += v10 * shw2[col * 3 + d] + v11 * shw2[(col + 1) * 3 + d];
            }
        }
#pragma unroll
        for (int d = 0; d < 3; d++) {
            p0[d] += __shfl_xor_sync(0xFFFFFFFFu, p0[d], 1);
            p0[d] += __shfl_xor_sync(0xFFFFFFFFu, p0[d], 2);
            p1[d] += __shfl_xor_sync(0xFFFFFFFFu, p1[d], 1);
            p1[d] += __shfl_xor_sync(0xFFFFFFFFu, p1[d], 2);
        }
        if (q == 0) {
            int row0 = r0 + g, row1 = row0 + 8;
#pragma unroll
            for (int d = 0; d < 3; d++) {
                sPart[(warp_n * 128 + row0) * 3 + d] = p0[d];
                sPart[(warp_n * 128 + row1) * 3 + d] = p1[d];
            }
        }
        __syncthreads();
        if (tid < 128) {
            int orow = blockIdx.x * 128 + tid;
            if (orow < M) {
#pragma unroll
                for (int d = 0; d < 3; d++)
                    delta[orow * 3 + d] = tanhf(sPart[tid * 3 + d] +
                                                sPart[(128 + tid) * 3 + d] + hb2[d]);
            }
        }
        return;
    }

#pragma unroll
    for (int ct = 0; ct < 8; ct++) {
        int col = (warp_n * 8 + ct) * 8 + q * 2;
        float b0 = sbias[col], b1 = sbias[col + 1];
        float v00 = acc[ct][0] + b0, v01 = acc[ct][1] + b1;
        float v10 = acc[ct][2] + b0, v11 = acc[ct][3] + b1;
        if (act == 1) {
            v00 = leaky(v00); v01 = leaky(v01);
            v10 = leaky(v10); v11 = leaky(v11);
        }
        if (orow0 < M) {
            if (resid) {
                float2 r = *(const float2*)(resid + (size_t)orow0 * CC + col);
                v00 += r.x; v01 += r.y;
            }
            *(float2*)(out + (size_t)orow0 * CC + col) = make_float2(v00, v01);
        }
        if (orow1 < M) {
            if (resid) {
                float2 r = *(const float2*)(resid + (size_t)orow1 * CC + col);
                v10 += r.x; v11 += r.y;
            }
            *(float2*)(out + (size_t)orow1 * CC + col) = make_float2(v10, v11);
        }
    }
}

// ======================= CSR build (R5, proven) ============================
__global__ void zero_int_kernel(int* __restrict__ p, int n)
{
    int i = blockIdx.x * 256 + threadIdx.x;
    if (i < n) p[i] = 0;
}

__global__ void hist_kernel(const void* __restrict__ ei_raw, int* __restrict__ deg,
                            int E, int M)
{
    int e = blockIdx.x * 256 + threadIdx.x;
    if (e >= E) return;
    int i = g_is64 ? (int)((const long long*)ei_raw)[E + e]
                   : ((const int*)ei_raw)[E + e];
    if ((unsigned)i < (unsigned)M) atomicAdd(&deg[i], 1);
}

__global__ void scan1_kernel(const int* __restrict__ deg, int* __restrict__ off,
                             int* __restrict__ bsum, int M)
{
    __shared__ int s[256];
    int tid = threadIdx.x;
    int i = blockIdx.x * 256 + tid;
    int d = (i < M) ? deg[i] : 0;
    s[tid] = d;
    __syncthreads();
#pragma unroll
    for (int o = 1; o < 256; o <<= 1) {
        int t = (tid >= o) ? s[tid - o] : 0;
        __syncthreads();
        s[tid] += t;
        __syncthreads();
    }
    if (i < M) off[i] = s[tid] - d;       // exclusive
    if (tid == 255) bsum[blockIdx.x] = s[255];
}

__global__ void scan2_kernel(int* __restrict__ bsum, int nb)
{
    __shared__ int s[256];
    int tid = threadIdx.x;
    int d = (tid < nb) ? bsum[tid] : 0;
    s[tid] = d;
    __syncthreads();
#pragma unroll
    for (int o = 1; o < 256; o <<= 1) {
        int t = (tid >= o) ? s[tid - o] : 0;
        __syncthreads();
        s[tid] += t;
        __syncthreads();
    }
    if (tid < nb) bsum[tid] = s[tid] - d;  // exclusive
}

__global__ void scan3_kernel(int* __restrict__ off, int* __restrict__ cur,
                             const int* __restrict__ bsum, int M)
{
    int i = blockIdx.x * 256 + threadIdx.x;
    if (i >= M) return;
    int v = off[i] + bsum[blockIdx.x];
    off[i] = v;
    cur[i] = v;
}

__global__ void scatter_kernel(const void* __restrict__ ei_raw,
                               int* __restrict__ cur, int* __restrict__ ssrc,
                               int E, int M)
{
    int e = blockIdx.x * 256 + threadIdx.x;
    if (e >= E) return;
    int j, i;
    if (g_is64) {
        const long long* ei = (const long long*)ei_raw;
        j = (int)ei[e];
        i = (int)ei[E + e];
    } else {
        const int* ei = (const int*)ei_raw;
        j = ei[e];
        i = ei[E + e];
    }
    if ((unsigned)j >= (unsigned)M || (unsigned)i >= (unsigned)M) return;
    int pos = atomicAdd(&cur[i], 1);
    ssrc[pos] = j;
}

// ---------------------------------------------------------------------------
// Aggregate: one warp per node, register accumulation, single store.
// ---------------------------------------------------------------------------
__global__ __launch_bounds__(256) void aggregate_kernel(
    const int* __restrict__ off, const int* __restrict__ deg,
    const int* __restrict__ ssrc, const float* __restrict__ pos,
    const float* __restrict__ delta, const float* __restrict__ y,
    const float* __restrict__ f_w, float* __restrict__ aggr, int M)
{
    int node = (blockIdx.x * 256 + threadIdx.x) >> 5;
    int lane = threadIdx.x & 31;
    if (node >= M) return;

    int c = lane * 4;
    float4 w0 = *(const float4*)(f_w + 0 * CC + c);
    float4 w1 = *(const float4*)(f_w + 1 * CC + c);
    float4 w2 = *(const float4*)(f_w + 2 * CC + c);
    float b0 = delta[node * 3 + 0] - pos[node * 3 + 0];
    float b1 = delta[node * 3 + 1] - pos[node * 3 + 1];
    float b2 = delta[node * 3 + 2] - pos[node * 3 + 2];

    float4 acc = make_float4(0.f, 0.f, 0.f, 0.f);
    int s = off[node], n = deg[node];
    int e = 0;
    // 2-way unrolled for MLP
    for (; e + 2 <= n; e += 2) {
        int ja = __ldg(&ssrc[s + e]);
        int jb = __ldg(&ssrc[s + e + 1]);
        float ra0 = __ldg(&pos[ja * 3 + 0]) + b0;
        float ra1 = __ldg(&pos[ja * 3 + 1]) + b1;
        float ra2 = __ldg(&pos[ja * 3 + 2]) + b2;
        float rb0 = __ldg(&pos[jb * 3 + 0]) + b0;
        float rb1 = __ldg(&pos[jb * 3 + 1]) + b1;
        float rb2 = __ldg(&pos[jb * 3 + 2]) + b2;
        float4 ya = *(const float4*)(y + (size_t)ja * CC + c);
        float4 yb = *(const float4*)(y + (size_t)jb * CC + c);
        acc.x += leaky(ya.x + ra0 * w0.x + ra1 * w1.x + ra2 * w2.x)
               + leaky(yb.x + rb0 * w0.x + rb1 * w1.x + rb2 * w2.x);
        acc.y += leaky(ya.y + ra0 * w0.y + ra1 * w1.y + ra2 * w2.y)
               + leaky(yb.y + rb0 * w0.y + rb1 * w1.y + rb2 * w2.y);
        acc.z += leaky(ya.z + ra0 * w0.z + ra1 * w1.z + ra2 * w2.z)
               + leaky(yb.z + rb0 * w0.z + rb1 * w1.z + rb2 * w2.z);
        acc.w += leaky(ya.w + ra0 * w0.w + ra1 * w1.w + ra2 * w2.w)
               + leaky(yb.w + rb0 * w0.w + rb1 * w1.w + rb2 * w2.w);
    }
    for (; e < n; e++) {
        int j = __ldg(&ssrc[s + e]);
        float r0 = __ldg(&pos[j * 3 + 0]) + b0;
        float r1 = __ldg(&pos[j * 3 + 1]) + b1;
        float r2 = __ldg(&pos[j * 3 + 2]) + b2;
        float4 yv = *(const float4*)(y + (size_t)j * CC + c);
        acc.x += leaky(yv.x + r0 * w0.x + r1 * w1.x + r2 * w2.x);
        acc.y += leaky(yv.y + r0 * w0.y + r1 * w1.y + r2 * w2.y);
        acc.z += leaky(yv.z + r0 * w0.z + r1 * w1.z + r2 * w2.z);
        acc.w += leaky(yv.w + r0 * w0.w + r1 * w1.w + r2 * w2.w);
    }
    *(float4*)(aggr + (size_t)node * CC + c) = acc;
}

// ---------------------------------------------------------------------------
extern "C" void kernel_launch(void* const* d_in, const int* in_sizes, int n_in,
                              void* d_out, int out_size)
{
    const float* x      = (const float*)d_in[0];
    const float* pos    = (const float*)d_in[1];
    const void*  ei     = d_in[2];
    const float* h_w1   = (const float*)d_in[3];
    const float* h_b1   = (const float*)d_in[4];
    const float* h_w2   = (const float*)d_in[5];
    const float* h_b2   = (const float*)d_in[6];
    const float* f_w    = (const float*)d_in[7];
    const float* f_b    = (const float*)d_in[8];
    const float* g_w1   = (const float*)d_in[9];
    const float* g_b1   = (const float*)d_in[10];
    const float* g_w2   = (const float*)d_in[11];
    const float* g_b2   = (const float*)d_in[12];
    float* out = (float*)d_out;

    const int M = in_sizes[0] / CC;  // 50000
    const int E = in_sizes[2] / 2;   // 800000

    float *y, *t, *aggr, *delta;
    int *deg, *off, *cur, *ssrc, *bsum;
    uint4* fragW;
    cudaGetSymbolAddress((void**)&y,     g_y);
    cudaGetSymbolAddress((void**)&t,     g_t);
    cudaGetSymbolAddress((void**)&aggr,  g_aggr);
    cudaGetSymbolAddress((void**)&delta, g_delta);
    cudaGetSymbolAddress((void**)&deg,   g_deg);
    cudaGetSymbolAddress((void**)&off,   g_off);
    cudaGetSymbolAddress((void**)&cur,   g_cur);
    cudaGetSymbolAddress((void**)&ssrc,  g_ssrc);
    cudaGetSymbolAddress((void**)&bsum,  g_bsum);
    cudaGetSymbolAddress((void**)&fragW, g_fragW);

    static int smem_set = 0;
    if (!smem_set) {
        cudaFuncSetAttribute(gemm_mma, cudaFuncAttributeMaxDynamicSharedMemorySize, SM_TOT);
        smem_set = 1;
    }

    const int gcta = (M + 127) / 128;
    const int ncta = (M + 255) / 256;   // <=256 blocks for M<=65536
    const int ecta = (E + 255) / 256;

    // --- prep ---
    detect_dtype_kernel<<<1, 32>>>((const int*)ei, 2048);
    prep_weights_kernel<<<(4 * 4096 + 255) / 256, 256>>>(h_w1, f_w + 3 * CC, g_w1, g_w2);

    // --- CSR build ---
    zero_int_kernel<<<ncta, 256>>>(deg, M);
    hist_kernel<<<ecta, 256>>>(ei, deg, E, M);
    scan1_kernel<<<ncta, 256>>>(deg, off, bsum, M);
    scan2_kernel<<<1, 256>>>(bsum, ncta);
    scan3_kernel<<<ncta, 256>>>(off, cur, bsum, M);
    scatter_kernel<<<ecta, 256>>>(ei, cur, ssrc, E, M);

    // --- GEMMs + delta ---
    // delta = tanh(leaky(x @ h_w1 + h_b1) @ h_w2 + h_b2)  (fused)
    gemm_mma<<<gcta, 512, SM_TOT>>>(x, fragW + 0 * 4096, h_b1, nullptr, nullptr, M, 2,
                                    h_w2, h_b2, delta);
    // y = x @ f_w[3:, :] + f_b
    gemm_mma<<<gcta, 512, SM_TOT>>>(x, fragW + 1 * 4096, f_b, nullptr, y, M, 0,
                                    nullptr, nullptr, nullptr);

    // --- aggregation (no atomics) ---
    aggregate_kernel<<<(M * 32 + 255) / 256, 256>>>(off, deg, ssrc, pos, delta, y,
                                                    f_w, aggr, M);

    // t = leaky(aggr @ g_w1 + g_b1)
    gemm_mma<<<gcta, 512, SM_TOT>>>(aggr, fragW + 2 * 4096, g_b1, nullptr, t, M, 1,
                                    nullptr, nullptr, nullptr);
    // out = t @ g_w2 + g_b2 + x
    gemm_mma<<<gcta, 512, SM_TOT>>>(t, fragW + 3 * 4096, g_b2, x, out, M, 0,
                                    nullptr, nullptr, nullptr);
}

// round 13
// speedup vs baseline: 1.2955x; 1.0516x over previous
#include <cuda_runtime.h>
#include <cuda_bf16.h>
#include <cstdint>

#define NN 50000
#define EE 800000
#define CC 128
#define NEG 0.01f

// Scratch (no allocation allowed -> __device__ globals)
__device__ float g_y[NN * CC];
__device__ float g_t[NN * CC];
__device__ float g_aggr[NN * CC];
__device__ float g_delta[NN * 3];
__device__ int   g_is64;
// CSR scratch
__device__ int g_deg[NN];
__device__ int g_off[NN];
__device__ int g_cur[NN];
__device__ int g_ssrc[EE];
__device__ int g_bsum[256];
// Fragment-major weights: per matrix 4096 x uint4 {bhi0,bhi1,blo0,blo1} = 64KB
// index (per matrix): ct*256 + kc*32 + g*4 + q
__device__ uint4 g_fragW[4 * 4096];

__device__ __forceinline__ float leaky(float v) {
    return v >= 0.0f ? v : NEG * v;
}

// ---------------------------------------------------------------------------
__global__ void detect_dtype_kernel(const int* __restrict__ ei32, int n_words)
{
    if (blockIdx.x == 0 && threadIdx.x == 0) {
        int all_hi_zero = 1;
        int pairs = n_words / 2;
        if (pairs > 1024) pairs = 1024;
        for (int p = 0; p < pairs; ++p) {
            if (ei32[2 * p + 1] != 0) { all_hi_zero = 0; break; }
        }
        g_is64 = all_hi_zero;
    }
}

// ---------------------------------------------------------------------------
__device__ __forceinline__ uint32_t pack_hi(float a, float b) {
    __nv_bfloat16 ha = __float2bfloat16(a), hb = __float2bfloat16(b);
    return (uint32_t)__bfloat16_as_ushort(ha) | ((uint32_t)__bfloat16_as_ushort(hb) << 16);
}
__device__ __forceinline__ uint32_t pack_lo(float a, float b) {
    __nv_bfloat16 ha = __float2bfloat16(a), hb = __float2bfloat16(b);
    __nv_bfloat16 la = __float2bfloat16(a - __bfloat162float(ha));
    __nv_bfloat16 lb = __float2bfloat16(b - __bfloat162float(hb));
    return (uint32_t)__bfloat16_as_ushort(la) | ((uint32_t)__bfloat16_as_ushort(lb) << 16);
}

__global__ void prep_weights_kernel(const float* __restrict__ w0,
                                    const float* __restrict__ w1,
                                    const float* __restrict__ w2,
                                    const float* __restrict__ w3)
{
    int idx = blockIdx.x * 256 + threadIdx.x;   // 4*4096 entries
    if (idx >= 4 * 4096) return;
    int m = idx >> 12;
    int rem = idx & 4095;
    int col = rem >> 5;        // 0..127
    int kc  = (rem >> 2) & 7;  // 0..7
    int q   = rem & 3;         // 0..3
    const float* w = (m == 0) ? w0 : (m == 1) ? w1 : (m == 2) ? w2 : w3;
    int k0 = kc * 16 + 2 * q;
    float a0 = w[(k0 + 0) * CC + col];
    float a1 = w[(k0 + 1) * CC + col];
    float a2 = w[(k0 + 8) * CC + col];
    float a3 = w[(k0 + 9) * CC + col];
    uint4 v;
    v.x = pack_hi(a0, a1);
    v.y = pack_hi(a2, a3);
    v.z = pack_lo(a0, a1);
    v.w = pack_lo(a2, a3);
    int ct = col >> 3, g = col & 7;
    g_fragW[m * 4096 + ct * 256 + kc * 32 + g * 4 + q] = v;
}

// ---------------------------------------------------------------------------
__device__ __forceinline__ void mma_bf16(float* c, const uint32_t* a, const uint32_t* b)
{
    asm volatile(
        "mma.sync.aligned.m16n8k16.row.col.f32.bf16.bf16.f32 "
        "{%0,%1,%2,%3}, {%4,%5,%6,%7}, {%8,%9}, {%0,%1,%2,%3};"
        : "+f"(c[0]), "+f"(c[1]), "+f"(c[2]), "+f"(c[3])
        : "r"(a[0]), "r"(a[1]), "r"(a[2]), "r"(a[3]), "r"(b[0]), "r"(b[1]));
}

__device__ __forceinline__ void cvt_hilo(float2 f, uint32_t& hi, uint32_t& lo)
{
    __nv_bfloat16 hx = __float2bfloat16(f.x);
    __nv_bfloat16 hy = __float2bfloat16(f.y);
    __nv_bfloat16 lx = __float2bfloat16(f.x - __bfloat162float(hx));
    __nv_bfloat16 ly = __float2bfloat16(f.y - __bfloat162float(hy));
    hi = (uint32_t)__bfloat16_as_ushort(hx) | ((uint32_t)__bfloat16_as_ushort(hy) << 16);
    lo = (uint32_t)__bfloat16_as_ushort(lx) | ((uint32_t)__bfloat16_as_ushort(ly) << 16);
}

// ---------------------------------------------------------------------------
// Split-bf16 GEMM (R10, proven): 512 threads / 16 warps, warp tile 16x64.
// W in smem fragment-major; A staged fp32 in 2 K-chunks of 64 cols (stride 72).
// 2 CTAs/SM. act: 0 none(+resid), 1 leaky, 2 delta-fused.
// smem: A [0, 36864); W [36864, 102400); bias [102400,+512); hw2 [102912,+1536)
// ---------------------------------------------------------------------------
#define SM_W    36864
#define SM_BIAS 102400
#define SM_HW2  102912
#define SM_TOT  104448

__global__ __launch_bounds__(512, 2) void gemm_mma(
    const float* __restrict__ A, const uint4* __restrict__ fragW,
    const float* __restrict__ bias, const float* __restrict__ resid,
    float* __restrict__ out, int M, int act,
    const float* __restrict__ hw2, const float* __restrict__ hb2,
    float* __restrict__ delta)
{
    extern __shared__ char sm[];
    float* sA = (float*)sm;                       // [128][72]
    uint4* sW = (uint4*)(sm + SM_W);              // 4096 uint4
    const int tid = threadIdx.x;

#pragma unroll
    for (int i = 0; i < 8; i++)
        sW[tid + i * 512] = fragW[tid + i * 512];
    if (tid < 128) ((float*)(sm + SM_BIAS))[tid] = bias[tid];
    if (act == 2) {
        for (int i = tid; i < 384; i += 512)
            ((float*)(sm + SM_HW2))[i] = hw2[i];
    }

    const int warp = tid >> 5, lane = tid & 31;
    const int g = lane >> 2, q = lane & 3;
    const int warp_m = warp >> 1, warp_n = warp & 1;
    const int r0 = warp_m * 16;

    float acc[8][4];
#pragma unroll
    for (int ct = 0; ct < 8; ct++)
#pragma unroll
        for (int c = 0; c < 4; c++) acc[ct][c] = 0.f;

    const int srow = tid & 127;
    const int sseg = (tid >> 7) * 4;          // float4 seg base 0,4,8,12
    const int grow = blockIdx.x * 128 + srow;
    const float* a0base = sA + (r0 + g) * 72;
    const float* a1base = sA + (r0 + g + 8) * 72;

    for (int half = 0; half < 2; half++) {
        {
            const float4* src = (grow < M)
                ? (const float4*)(A + (size_t)grow * CC + half * 64) : nullptr;
            float* dst = sA + srow * 72;
#pragma unroll
            for (int i = 0; i < 4; i++) {
                float4 v = src ? src[sseg + i] : make_float4(0.f, 0.f, 0.f, 0.f);
                *(float4*)(dst + (sseg + i) * 4) = v;
            }
        }
        __syncthreads();

#pragma unroll
        for (int kc2 = 0; kc2 < 4; kc2++) {
            const int kc = half * 4 + kc2;
            const int k0 = kc2 * 16 + q * 2;
            float2 f00 = *(const float2*)(a0base + k0);
            float2 f10 = *(const float2*)(a1base + k0);
            float2 f01 = *(const float2*)(a0base + k0 + 8);
            float2 f11 = *(const float2*)(a1base + k0 + 8);
            uint32_t ahi[4], alo[4];
            cvt_hilo(f00, ahi[0], alo[0]);
            cvt_hilo(f10, ahi[1], alo[1]);
            cvt_hilo(f01, ahi[2], alo[2]);
            cvt_hilo(f11, ahi[3], alo[3]);

            const uint4* wbase = sW + kc * 32 + g * 4 + q;
#pragma unroll
            for (int ct = 0; ct < 8; ct++) {
                uint4 wv = wbase[(warp_n * 8 + ct) * 256];
                uint32_t bh[2] = { wv.x, wv.y };
                uint32_t bl[2] = { wv.z, wv.w };
                mma_bf16(acc[ct], ahi, bh);
                mma_bf16(acc[ct], ahi, bl);
                mma_bf16(acc[ct], alo, bh);
            }
        }
        __syncthreads();
    }

    const float* sbias = (const float*)(sm + SM_BIAS);
    int orow0 = blockIdx.x * 128 + r0 + g;
    int orow1 = orow0 + 8;

    if (act == 2) {
        const float* shw2 = (const float*)(sm + SM_HW2);
        float* sPart = (float*)(sm + SM_W);   // [2][128][3] floats (W dead)
        float p0[3] = {0.f, 0.f, 0.f}, p1[3] = {0.f, 0.f, 0.f};
#pragma unroll
        for (int ct = 0; ct < 8; ct++) {
            int col = (warp_n * 8 + ct) * 8 + q * 2;
            float b0 = sbias[col], b1 = sbias[col + 1];
            float v00 = leaky(acc[ct][0] + b0), v01 = leaky(acc[ct][1] + b1);
            float v10 = leaky(acc[ct][2] + b0), v11 = leaky(acc[ct][3] + b1);
#pragma unroll
            for (int d = 0; d < 3; d++) {
                p0[d] += v00 * shw2[col * 3 + d] + v01 * shw2[(col + 1) * 3 + d];
                p1[d] += v10 * shw2[col * 3 + d] + v11 * shw2[(col + 1) * 3 + d];
            }
        }
#pragma unroll
        for (int d = 0; d < 3; d++) {
            p0[d] += __shfl_xor_sync(0xFFFFFFFFu, p0[d], 1);
            p0[d] += __shfl_xor_sync(0xFFFFFFFFu, p0[d], 2);
            p1[d] += __shfl_xor_sync(0xFFFFFFFFu, p1[d], 1);
            p1[d] += __shfl_xor_sync(0xFFFFFFFFu, p1[d], 2);
        }
        if (q == 0) {
            int row0 = r0 + g, row1 = row0 + 8;
#pragma unroll
            for (int d = 0; d < 3; d++) {
                sPart[(warp_n * 128 + row0) * 3 + d] = p0[d];
                sPart[(warp_n * 128 + row1) * 3 + d] = p1[d];
            }
        }
        __syncthreads();
        if (tid < 128) {
            int orow = blockIdx.x * 128 + tid;
            if (orow < M) {
#pragma unroll
                for (int d = 0; d < 3; d++)
                    delta[orow * 3 + d] = tanhf(sPart[tid * 3 + d] +
                                                sPart[(128 + tid) * 3 + d] + hb2[d]);
            }
        }
        return;
    }

#pragma unroll
    for (int ct = 0; ct < 8; ct++) {
        int col = (warp_n * 8 + ct) * 8 + q * 2;
        float b0 = sbias[col], b1 = sbias[col + 1];
        float v00 = acc[ct][0] + b0, v01 = acc[ct][1] + b1;
        float v10 = acc[ct][2] + b0, v11 = acc[ct][3] + b1;
        if (act == 1) {
            v00 = leaky(v00); v01 = leaky(v01);
            v10 = leaky(v10); v11 = leaky(v11);
        }
        if (orow0 < M) {
            if (resid) {
                float2 r = *(const float2*)(resid + (size_t)orow0 * CC + col);
                v00 += r.x; v01 += r.y;
            }
            *(float2*)(out + (size_t)orow0 * CC + col) = make_float2(v00, v01);
        }
        if (orow1 < M) {
            if (resid) {
                float2 r = *(const float2*)(resid + (size_t)orow1 * CC + col);
                v10 += r.x; v11 += r.y;
            }
            *(float2*)(out + (size_t)orow1 * CC + col) = make_float2(v10, v11);
        }
    }
}

// ======================= CSR build =========================================
__global__ void zero_int_kernel(int* __restrict__ p, int n)
{
    int i = blockIdx.x * 256 + threadIdx.x;
    if (i < n) p[i] = 0;
}

// 4 edges per thread for MLP
__global__ void hist_kernel(const void* __restrict__ ei_raw, int* __restrict__ deg,
                            int E, int M)
{
    int base = (blockIdx.x * 256 + threadIdx.x) * 4;
    if (base >= E) return;
    int is64 = g_is64;
    const long long* e64 = (const long long*)ei_raw;
    const int* e32 = (const int*)ei_raw;
    int idx[4];
#pragma unroll
    for (int k = 0; k < 4; k++) {
        int e = base + k;
        idx[k] = (e < E) ? (is64 ? (int)e64[E + e] : e32[E + e]) : -1;
    }
#pragma unroll
    for (int k = 0; k < 4; k++)
        if ((unsigned)idx[k] < (unsigned)M) atomicAdd(&deg[idx[k]], 1);
}

__global__ void scan1_kernel(const int* __restrict__ deg, int* __restrict__ off,
                             int* __restrict__ bsum, int M)
{
    __shared__ int s[256];
    int tid = threadIdx.x;
    int i = blockIdx.x * 256 + tid;
    int d = (i < M) ? deg[i] : 0;
    s[tid] = d;
    __syncthreads();
#pragma unroll
    for (int o = 1; o < 256; o <<= 1) {
        int t = (tid >= o) ? s[tid - o] : 0;
        __syncthreads();
        s[tid] += t;
        __syncthreads();
    }
    if (i < M) off[i] = s[tid] - d;       // exclusive
    if (tid == 255) bsum[blockIdx.x] = s[255];
}

__global__ void scan2_kernel(int* __restrict__ bsum, int nb)
{
    __shared__ int s[256];
    int tid = threadIdx.x;
    int d = (tid < nb) ? bsum[tid] : 0;
    s[tid] = d;
    __syncthreads();
#pragma unroll
    for (int o = 1; o < 256; o <<= 1) {
        int t = (tid >= o) ? s[tid - o] : 0;
        __syncthreads();
        s[tid] += t;
        __syncthreads();
    }
    if (tid < nb) bsum[tid] = s[tid] - d;  // exclusive
}

__global__ void scan3_kernel(int* __restrict__ off, int* __restrict__ cur,
                             const int* __restrict__ bsum, int M)
{
    int i = blockIdx.x * 256 + threadIdx.x;
    if (i >= M) return;
    int v = off[i] + bsum[blockIdx.x];
    off[i] = v;
    cur[i] = v;
}

// 4 edges per thread for MLP
__global__ void scatter_kernel(const void* __restrict__ ei_raw,
                               int* __restrict__ cur, int* __restrict__ ssrc,
                               int E, int M)
{
    int base = (blockIdx.x * 256 + threadIdx.x) * 4;
    if (base >= E) return;
    int is64 = g_is64;
    const long long* e64 = (const long long*)ei_raw;
    const int* e32 = (const int*)ei_raw;
    int js[4], is_[4];
#pragma unroll
    for (int k = 0; k < 4; k++) {
        int e = base + k;
        if (e < E) {
            js[k]  = is64 ? (int)e64[e]     : e32[e];
            is_[k] = is64 ? (int)e64[E + e] : e32[E + e];
        } else {
            js[k] = -1; is_[k] = -1;
        }
    }
#pragma unroll
    for (int k = 0; k < 4; k++) {
        if ((unsigned)js[k] < (unsigned)M && (unsigned)is_[k] < (unsigned)M) {
            int pos = atomicAdd(&cur[is_[k]], 1);
            ssrc[pos] = js[k];
        }
    }
}

// ---------------------------------------------------------------------------
// Aggregate: one warp per node, register accumulation, single store.
// ---------------------------------------------------------------------------
__global__ __launch_bounds__(256) void aggregate_kernel(
    const int* __restrict__ off, const int* __restrict__ deg,
    const int* __restrict__ ssrc, const float* __restrict__ pos,
    const float* __restrict__ delta, const float* __restrict__ y,
    const float* __restrict__ f_w, float* __restrict__ aggr, int M)
{
    int node = (blockIdx.x * 256 + threadIdx.x) >> 5;
    int lane = threadIdx.x & 31;
    if (node >= M) return;

    int c = lane * 4;
    float4 w0 = *(const float4*)(f_w + 0 * CC + c);
    float4 w1 = *(const float4*)(f_w + 1 * CC + c);
    float4 w2 = *(const float4*)(f_w + 2 * CC + c);
    float b0 = delta[node * 3 + 0] - pos[node * 3 + 0];
    float b1 = delta[node * 3 + 1] - pos[node * 3 + 1];
    float b2 = delta[node * 3 + 2] - pos[node * 3 + 2];

    float4 acc = make_float4(0.f, 0.f, 0.f, 0.f);
    int s = off[node], n = deg[node];
    int e = 0;
    for (; e + 2 <= n; e += 2) {
        int ja = __ldg(&ssrc[s + e]);
        int jb = __ldg(&ssrc[s + e + 1]);
        float ra0 = __ldg(&pos[ja * 3 + 0]) + b0;
        float ra1 = __ldg(&pos[ja * 3 + 1]) + b1;
        float ra2 = __ldg(&pos[ja * 3 + 2]) + b2;
        float rb0 = __ldg(&pos[jb * 3 + 0]) + b0;
        float rb1 = __ldg(&pos[jb * 3 + 1]) + b1;
        float rb2 = __ldg(&pos[jb * 3 + 2]) + b2;
        float4 ya = *(const float4*)(y + (size_t)ja * CC + c);
        float4 yb = *(const float4*)(y + (size_t)jb * CC + c);
        acc.x += leaky(ya.x + ra0 * w0.x + ra1 * w1.x + ra2 * w2.x)
               + leaky(yb.x + rb0 * w0.x + rb1 * w1.x + rb2 * w2.x);
        acc.y += leaky(ya.y + ra0 * w0.y + ra1 * w1.y + ra2 * w2.y)
               + leaky(yb.y + rb0 * w0.y + rb1 * w1.y + rb2 * w2.y);
        acc.z += leaky(ya.z + ra0 * w0.z + ra1 * w1.z + ra2 * w2.z)
               + leaky(yb.z + rb0 * w0.z + rb1 * w1.z + rb2 * w2.z);
        acc.w += leaky(ya.w + ra0 * w0.w + ra1 * w1.w + ra2 * w2.w)
               + leaky(yb.w + rb0 * w0.w + rb1 * w1.w + rb2 * w2.w);
    }
    for (; e < n; e++) {
        int j = __ldg(&ssrc[s + e]);
        float r0 = __ldg(&pos[j * 3 + 0]) + b0;
        float r1 = __ldg(&pos[j * 3 + 1]) + b1;
        float r2 = __ldg(&pos[j * 3 + 2]) + b2;
        float4 yv = *(const float4*)(y + (size_t)j * CC + c);
        acc.x += leaky(yv.x + r0 * w0.x + r1 * w1.x + r2 * w2.x);
        acc.y += leaky(yv.y + r0 * w0.y + r1 * w1.y + r2 * w2.y);
        acc.z += leaky(yv.z + r0 * w0.z + r1 * w1.z + r2 * w2.z);
        acc.w += leaky(yv.w + r0 * w0.w + r1 * w1.w + r2 * w2.w);
    }
    *(float4*)(aggr + (size_t)node * CC + c) = acc;
}

// ---------------------------------------------------------------------------
extern "C" void kernel_launch(void* const* d_in, const int* in_sizes, int n_in,
                              void* d_out, int out_size)
{
    const float* x      = (const float*)d_in[0];
    const float* pos    = (const float*)d_in[1];
    const void*  ei     = d_in[2];
    const float* h_w1   = (const float*)d_in[3];
    const float* h_b1   = (const float*)d_in[4];
    const float* h_w2   = (const float*)d_in[5];
    const float* h_b2   = (const float*)d_in[6];
    const float* f_w    = (const float*)d_in[7];
    const float* f_b    = (const float*)d_in[8];
    const float* g_w1   = (const float*)d_in[9];
    const float* g_b1   = (const float*)d_in[10];
    const float* g_w2   = (const float*)d_in[11];
    const float* g_b2   = (const float*)d_in[12];
    float* out = (float*)d_out;

    const int M = in_sizes[0] / CC;  // 50000
    const int E = in_sizes[2] / 2;   // 800000

    float *y, *t, *aggr, *delta;
    int *deg, *off, *cur, *ssrc, *bsum;
    uint4* fragW;
    cudaGetSymbolAddress((void**)&y,     g_y);
    cudaGetSymbolAddress((void**)&t,     g_t);
    cudaGetSymbolAddress((void**)&aggr,  g_aggr);
    cudaGetSymbolAddress((void**)&delta, g_delta);
    cudaGetSymbolAddress((void**)&deg,   g_deg);
    cudaGetSymbolAddress((void**)&off,   g_off);
    cudaGetSymbolAddress((void**)&cur,   g_cur);
    cudaGetSymbolAddress((void**)&ssrc,  g_ssrc);
    cudaGetSymbolAddress((void**)&bsum,  g_bsum);
    cudaGetSymbolAddress((void**)&fragW, g_fragW);

    static int inited = 0;
    static cudaStream_t sB = nullptr;
    static cudaEvent_t evFork = nullptr, evJoin = nullptr;
    if (!inited) {
        cudaFuncSetAttribute(gemm_mma, cudaFuncAttributeMaxDynamicSharedMemorySize, SM_TOT);
        cudaStreamCreateWithFlags(&sB, cudaStreamNonBlocking);
        cudaEventCreateWithFlags(&evFork, cudaEventDisableTiming);
        cudaEventCreateWithFlags(&evJoin, cudaEventDisableTiming);
        inited = 1;
    }

    const int gcta = (M + 127) / 128;
    const int ncta = (M + 255) / 256;        // <=256 blocks for M<=65536
    const int e4cta = (E + 1023) / 1024;     // 4 edges/thread

    // --- stream 0: dtype detect (needed by CSR branch) ---
    detect_dtype_kernel<<<1, 32>>>((const int*)ei, 2048);

    // --- fork: CSR build on side stream, GEMMs on main stream ---
    cudaEventRecord(evFork, 0);
    cudaStreamWaitEvent(sB, evFork, 0);

    // branch B: CSR build (depends only on edge_index)
    zero_int_kernel<<<ncta, 256, 0, sB>>>(deg, M);
    hist_kernel<<<e4cta, 256, 0, sB>>>(ei, deg, E, M);
    scan1_kernel<<<ncta, 256, 0, sB>>>(deg, off, bsum, M);
    scan2_kernel<<<1, 256, 0, sB>>>(bsum, ncta);
    scan3_kernel<<<ncta, 256, 0, sB>>>(off, cur, bsum, M);
    scatter_kernel<<<e4cta, 256, 0, sB>>>(ei, cur, ssrc, E, M);
    cudaEventRecord(evJoin, sB);

    // branch A (main stream): weight prep + first two GEMMs
    prep_weights_kernel<<<(4 * 4096 + 255) / 256, 256>>>(h_w1, f_w + 3 * CC, g_w1, g_w2);
    // delta = tanh(leaky(x @ h_w1 + h_b1) @ h_w2 + h_b2)  (fused)
    gemm_mma<<<gcta, 512, SM_TOT>>>(x, fragW + 0 * 4096, h_b1, nullptr, nullptr, M, 2,
                                    h_w2, h_b2, delta);
    // y = x @ f_w[3:, :] + f_b
    gemm_mma<<<gcta, 512, SM_TOT>>>(x, fragW + 1 * 4096, f_b, nullptr, y, M, 0,
                                    nullptr, nullptr, nullptr);

    // --- join: aggregation needs CSR + delta + y ---
    cudaStreamWaitEvent(0, evJoin, 0);
    aggregate_kernel<<<(M * 32 + 255) / 256, 256>>>(off, deg, ssrc, pos, delta, y,
                                                    f_w, aggr, M);

    // t = leaky(aggr @ g_w1 + g_b1)
    gemm_mma<<<gcta, 512, SM_TOT>>>(aggr, fragW + 2 * 4096, g_b1, nullptr, t, M, 1,
                                    nullptr, nullptr, nullptr);
    // out = t @ g_w2 + g_b2 + x
    gemm_mma<<<gcta, 512, SM_TOT>>>(t, fragW + 3 * 4096, g_b2, x, out, M, 0,
                                    nullptr, nullptr, nullptr);
}

// round 14
// speedup vs baseline: 1.3253x; 1.0230x over previous
#include <cuda_runtime.h>
#include <cuda_bf16.h>
#include <cstdint>

#define NN 50000
#define EE 800000
#define CC 128
#define NEG 0.01f

// Scratch (no allocation allowed -> __device__ globals)
__device__ float g_y[NN * CC];
__device__ float g_t[NN * CC];
__device__ float g_aggr[NN * CC];
__device__ float g_delta[NN * 3];
__device__ int   g_is64;
// CSR scratch
__device__ int g_deg[NN];
__device__ int g_off[NN];
__device__ int g_cur[NN];
__device__ int g_ssrc[EE];
__device__ int g_bsum[256];
// Fragment-major weights: per matrix 4096 x uint4 {bhi0,bhi1,blo0,blo1} = 64KB
// index (per matrix): ct*256 + kc*32 + g*4 + q
__device__ uint4 g_fragW[4 * 4096];

__device__ __forceinline__ float leaky(float v) {
    return v >= 0.0f ? v : NEG * v;
}

// ---------------------------------------------------------------------------
// Parallel dtype detect: int64 edge_index has zero high words at odd positions.
// ---------------------------------------------------------------------------
__global__ void detect_dtype_kernel(const int* __restrict__ ei32, int n_words)
{
    __shared__ int bad;
    if (threadIdx.x == 0) bad = 0;
    __syncthreads();
    int pairs = n_words / 2;
    for (int p = threadIdx.x; p < pairs; p += 256)
        if (ei32[2 * p + 1] != 0) bad = 1;
    __syncthreads();
    if (threadIdx.x == 0) g_is64 = bad ? 0 : 1;
}

// ---------------------------------------------------------------------------
__device__ __forceinline__ uint32_t pack_hi(float a, float b) {
    __nv_bfloat16 ha = __float2bfloat16(a), hb = __float2bfloat16(b);
    return (uint32_t)__bfloat16_as_ushort(ha) | ((uint32_t)__bfloat16_as_ushort(hb) << 16);
}
__device__ __forceinline__ uint32_t pack_lo(float a, float b) {
    __nv_bfloat16 ha = __float2bfloat16(a), hb = __float2bfloat16(b);
    __nv_bfloat16 la = __float2bfloat16(a - __bfloat162float(ha));
    __nv_bfloat16 lb = __float2bfloat16(b - __bfloat162float(hb));
    return (uint32_t)__bfloat16_as_ushort(la) | ((uint32_t)__bfloat16_as_ushort(lb) << 16);
}

__global__ void prep_weights_kernel(const float* __restrict__ w0,
                                    const float* __restrict__ w1,
                                    const float* __restrict__ w2,
                                    const float* __restrict__ w3)
{
    int idx = blockIdx.x * 256 + threadIdx.x;   // 4*4096 entries
    if (idx >= 4 * 4096) return;
    int m = idx >> 12;
    int rem = idx & 4095;
    int col = rem >> 5;        // 0..127
    int kc  = (rem >> 2) & 7;  // 0..7
    int q   = rem & 3;         // 0..3
    const float* w = (m == 0) ? w0 : (m == 1) ? w1 : (m == 2) ? w2 : w3;
    int k0 = kc * 16 + 2 * q;
    float a0 = w[(k0 + 0) * CC + col];
    float a1 = w[(k0 + 1) * CC + col];
    float a2 = w[(k0 + 8) * CC + col];
    float a3 = w[(k0 + 9) * CC + col];
    uint4 v;
    v.x = pack_hi(a0, a1);
    v.y = pack_hi(a2, a3);
    v.z = pack_lo(a0, a1);
    v.w = pack_lo(a2, a3);
    int ct = col >> 3, g = col & 7;
    g_fragW[m * 4096 + ct * 256 + kc * 32 + g * 4 + q] = v;
}

// ---------------------------------------------------------------------------
__device__ __forceinline__ void mma_bf16(float* c, const uint32_t* a, const uint32_t* b)
{
    asm volatile(
        "mma.sync.aligned.m16n8k16.row.col.f32.bf16.bf16.f32 "
        "{%0,%1,%2,%3}, {%4,%5,%6,%7}, {%8,%9}, {%0,%1,%2,%3};"
        : "+f"(c[0]), "+f"(c[1]), "+f"(c[2]), "+f"(c[3])
        : "r"(a[0]), "r"(a[1]), "r"(a[2]), "r"(a[3]), "r"(b[0]), "r"(b[1]));
}

__device__ __forceinline__ void cvt_hilo(float2 f, uint32_t& hi, uint32_t& lo)
{
    __nv_bfloat16 hx = __float2bfloat16(f.x);
    __nv_bfloat16 hy = __float2bfloat16(f.y);
    __nv_bfloat16 lx = __float2bfloat16(f.x - __bfloat162float(hx));
    __nv_bfloat16 ly = __float2bfloat16(f.y - __bfloat162float(hy));
    hi = (uint32_t)__bfloat16_as_ushort(hx) | ((uint32_t)__bfloat16_as_ushort(hy) << 16);
    lo = (uint32_t)__bfloat16_as_ushort(lx) | ((uint32_t)__bfloat16_as_ushort(ly) << 16);
}

// ---------------------------------------------------------------------------
// Split-bf16 GEMM (R10, proven): 512 threads / 16 warps, warp tile 16x64.
// W in smem fragment-major; A staged fp32 in 2 K-chunks of 64 cols (stride 72).
// 2 CTAs/SM. act: 0 none(+resid), 1 leaky, 2 delta-fused.
// smem: A [0, 36864); W [36864, 102400); bias [102400,+512); hw2 [102912,+1536)
// ---------------------------------------------------------------------------
#define SM_W    36864
#define SM_BIAS 102400
#define SM_HW2  102912
#define SM_TOT  104448

__global__ __launch_bounds__(512, 2) void gemm_mma(
    const float* __restrict__ A, const uint4* __restrict__ fragW,
    const float* __restrict__ bias, const float* __restrict__ resid,
    float* __restrict__ out, int M, int act,
    const float* __restrict__ hw2, const float* __restrict__ hb2,
    float* __restrict__ delta)
{
    extern __shared__ char sm[];
    float* sA = (float*)sm;                       // [128][72]
    uint4* sW = (uint4*)(sm + SM_W);              // 4096 uint4
    const int tid = threadIdx.x;

#pragma unroll
    for (int i = 0; i < 8; i++)
        sW[tid + i * 512] = fragW[tid + i * 512];
    if (tid < 128) ((float*)(sm + SM_BIAS))[tid] = bias[tid];
    if (act == 2) {
        for (int i = tid; i < 384; i += 512)
            ((float*)(sm + SM_HW2))[i] = hw2[i];
    }

    const int warp = tid >> 5, lane = tid & 31;
    const int g = lane >> 2, q = lane & 3;
    const int warp_m = warp >> 1, warp_n = warp & 1;
    const int r0 = warp_m * 16;

    float acc[8][4];
#pragma unroll
    for (int ct = 0; ct < 8; ct++)
#pragma unroll
        for (int c = 0; c < 4; c++) acc[ct][c] = 0.f;

    const int srow = tid & 127;
    const int sseg = (tid >> 7) * 4;          // float4 seg base 0,4,8,12
    const int grow = blockIdx.x * 128 + srow;
    const float* a0base = sA + (r0 + g) * 72;
    const float* a1base = sA + (r0 + g + 8) * 72;

    for (int half = 0; half < 2; half++) {
        {
            const float4* src = (grow < M)
                ? (const float4*)(A + (size_t)grow * CC + half * 64) : nullptr;
            float* dst = sA + srow * 72;
#pragma unroll
            for (int i = 0; i < 4; i++) {
                float4 v = src ? src[sseg + i] : make_float4(0.f, 0.f, 0.f, 0.f);
                *(float4*)(dst + (sseg + i) * 4) = v;
            }
        }
        __syncthreads();

#pragma unroll
        for (int kc2 = 0; kc2 < 4; kc2++) {
            const int kc = half * 4 + kc2;
            const int k0 = kc2 * 16 + q * 2;
            float2 f00 = *(const float2*)(a0base + k0);
            float2 f10 = *(const float2*)(a1base + k0);
            float2 f01 = *(const float2*)(a0base + k0 + 8);
            float2 f11 = *(const float2*)(a1base + k0 + 8);
            uint32_t ahi[4], alo[4];
            cvt_hilo(f00, ahi[0], alo[0]);
            cvt_hilo(f10, ahi[1], alo[1]);
            cvt_hilo(f01, ahi[2], alo[2]);
            cvt_hilo(f11, ahi[3], alo[3]);

            const uint4* wbase = sW + kc * 32 + g * 4 + q;
#pragma unroll
            for (int ct = 0; ct < 8; ct++) {
                uint4 wv = wbase[(warp_n * 8 + ct) * 256];
                uint32_t bh[2] = { wv.x, wv.y };
                uint32_t bl[2] = { wv.z, wv.w };
                mma_bf16(acc[ct], ahi, bh);
                mma_bf16(acc[ct], ahi, bl);
                mma_bf16(acc[ct], alo, bh);
            }
        }
        __syncthreads();
    }

    const float* sbias = (const float*)(sm + SM_BIAS);
    int orow0 = blockIdx.x * 128 + r0 + g;
    int orow1 = orow0 + 8;

    if (act == 2) {
        const float* shw2 = (const float*)(sm + SM_HW2);
        float* sPart = (float*)(sm + SM_W);   // [2][128][3] floats (W dead)
        float p0[3] = {0.f, 0.f, 0.f}, p1[3] = {0.f, 0.f, 0.f};
#pragma unroll
        for (int ct = 0; ct < 8; ct++) {
            int col = (warp_n * 8 + ct) * 8 + q * 2;
            float b0 = sbias[col], b1 = sbias[col + 1];
            float v00 = leaky(acc[ct][0] + b0), v01 = leaky(acc[ct][1] + b1);
            float v10 = leaky(acc[ct][2] + b0), v11 = leaky(acc[ct][3] + b1);
#pragma unroll
            for (int d = 0; d < 3; d++) {
                p0[d] += v00 * shw2[col * 3 + d] + v01 * shw2[(col + 1) * 3 + d];
                p1[d] += v10 * shw2[col * 3 + d] + v11 * shw2[(col + 1) * 3 + d];
            }
        }
#pragma unroll
        for (int d = 0; d < 3; d++) {
            p0[d] += __shfl_xor_sync(0xFFFFFFFFu, p0[d], 1);
            p0[d] += __shfl_xor_sync(0xFFFFFFFFu, p0[d], 2);
            p1[d] += __shfl_xor_sync(0xFFFFFFFFu, p1[d], 1);
            p1[d] += __shfl_xor_sync(0xFFFFFFFFu, p1[d], 2);
        }
        if (q == 0) {
            int row0 = r0 + g, row1 = row0 + 8;
#pragma unroll
            for (int d = 0; d < 3; d++) {
                sPart[(warp_n * 128 + row0) * 3 + d] = p0[d];
                sPart[(warp_n * 128 + row1) * 3 + d] = p1[d];
            }
        }
        __syncthreads();
        if (tid < 128) {
            int orow = blockIdx.x * 128 + tid;
            if (orow < M) {
#pragma unroll
                for (int d = 0; d < 3; d++)
                    delta[orow * 3 + d] = tanhf(sPart[tid * 3 + d] +
                                                sPart[(128 + tid) * 3 + d] + hb2[d]);
            }
        }
        return;
    }

#pragma unroll
    for (int ct = 0; ct < 8; ct++) {
        int col = (warp_n * 8 + ct) * 8 + q * 2;
        float b0 = sbias[col], b1 = sbias[col + 1];
        float v00 = acc[ct][0] + b0, v01 = acc[ct][1] + b1;
        float v10 = acc[ct][2] + b0, v11 = acc[ct][3] + b1;
        if (act == 1) {
            v00 = leaky(v00); v01 = leaky(v01);
            v10 = leaky(v10); v11 = leaky(v11);
        }
        if (orow0 < M) {
            if (resid) {
                float2 r = *(const float2*)(resid + (size_t)orow0 * CC + col);
                v00 += r.x; v01 += r.y;
            }
            *(float2*)(out + (size_t)orow0 * CC + col) = make_float2(v00, v01);
        }
        if (orow1 < M) {
            if (resid) {
                float2 r = *(const float2*)(resid + (size_t)orow1 * CC + col);
                v10 += r.x; v11 += r.y;
            }
            *(float2*)(out + (size_t)orow1 * CC + col) = make_float2(v10, v11);
        }
    }
}

// ======================= CSR build =========================================
__global__ void zero_int_kernel(int* __restrict__ p, int n)
{
    int i = blockIdx.x * 256 + threadIdx.x;
    if (i < n) p[i] = 0;
}

// 4 edges per thread for MLP
__global__ void hist_kernel(const void* __restrict__ ei_raw, int* __restrict__ deg,
                            int E, int M)
{
    int base = (blockIdx.x * 256 + threadIdx.x) * 4;
    if (base >= E) return;
    int is64 = g_is64;
    const long long* e64 = (const long long*)ei_raw;
    const int* e32 = (const int*)ei_raw;
    int idx[4];
#pragma unroll
    for (int k = 0; k < 4; k++) {
        int e = base + k;
        idx[k] = (e < E) ? (is64 ? (int)e64[E + e] : e32[E + e]) : -1;
    }
#pragma unroll
    for (int k = 0; k < 4; k++)
        if ((unsigned)idx[k] < (unsigned)M) atomicAdd(&deg[idx[k]], 1);
}

__global__ void scan1_kernel(const int* __restrict__ deg, int* __restrict__ off,
                             int* __restrict__ bsum, int M)
{
    __shared__ int s[256];
    int tid = threadIdx.x;
    int i = blockIdx.x * 256 + tid;
    int d = (i < M) ? deg[i] : 0;
    s[tid] = d;
    __syncthreads();
#pragma unroll
    for (int o = 1; o < 256; o <<= 1) {
        int t = (tid >= o) ? s[tid - o] : 0;
        __syncthreads();
        s[tid] += t;
        __syncthreads();
    }
    if (i < M) off[i] = s[tid] - d;       // exclusive
    if (tid == 255) bsum[blockIdx.x] = s[255];
}

__global__ void scan2_kernel(int* __restrict__ bsum, int nb)
{
    __shared__ int s[256];
    int tid = threadIdx.x;
    int d = (tid < nb) ? bsum[tid] : 0;
    s[tid] = d;
    __syncthreads();
#pragma unroll
    for (int o = 1; o < 256; o <<= 1) {
        int t = (tid >= o) ? s[tid - o] : 0;
        __syncthreads();
        s[tid] += t;
        __syncthreads();
    }
    if (tid < nb) bsum[tid] = s[tid] - d;  // exclusive
}

__global__ void scan3_kernel(int* __restrict__ off, int* __restrict__ cur,
                             const int* __restrict__ bsum, int M)
{
    int i = blockIdx.x * 256 + threadIdx.x;
    if (i >= M) return;
    int v = off[i] + bsum[blockIdx.x];
    off[i] = v;
    cur[i] = v;
}

// 4 edges per thread for MLP
__global__ void scatter_kernel(const void* __restrict__ ei_raw,
                               int* __restrict__ cur, int* __restrict__ ssrc,
                               int E, int M)
{
    int base = (blockIdx.x * 256 + threadIdx.x) * 4;
    if (base >= E) return;
    int is64 = g_is64;
    const long long* e64 = (const long long*)ei_raw;
    const int* e32 = (const int*)ei_raw;
    int js[4], is_[4];
#pragma unroll
    for (int k = 0; k < 4; k++) {
        int e = base + k;
        if (e < E) {
            js[k]  = is64 ? (int)e64[e]     : e32[e];
            is_[k] = is64 ? (int)e64[E + e] : e32[E + e];
        } else {
            js[k] = -1; is_[k] = -1;
        }
    }
#pragma unroll
    for (int k = 0; k < 4; k++) {
        if ((unsigned)js[k] < (unsigned)M && (unsigned)is_[k] < (unsigned)M) {
            int pos = atomicAdd(&cur[is_[k]], 1);
            ssrc[pos] = js[k];
        }
    }
}

// ---------------------------------------------------------------------------
// Aggregate: one warp per node, register accumulation, single store.
// ---------------------------------------------------------------------------
__global__ __launch_bounds__(256) void aggregate_kernel(
    const int* __restrict__ off, const int* __restrict__ deg,
    const int* __restrict__ ssrc, const float* __restrict__ pos,
    const float* __restrict__ delta, const float* __restrict__ y,
    const float* __restrict__ f_w, float* __restrict__ aggr, int M)
{
    int node = (blockIdx.x * 256 + threadIdx.x) >> 5;
    int lane = threadIdx.x & 31;
    if (node >= M) return;

    int c = lane * 4;
    float4 w0 = *(const float4*)(f_w + 0 * CC + c);
    float4 w1 = *(const float4*)(f_w + 1 * CC + c);
    float4 w2 = *(const float4*)(f_w + 2 * CC + c);
    float b0 = delta[node * 3 + 0] - pos[node * 3 + 0];
    float b1 = delta[node * 3 + 1] - pos[node * 3 + 1];
    float b2 = delta[node * 3 + 2] - pos[node * 3 + 2];

    float4 acc = make_float4(0.f, 0.f, 0.f, 0.f);
    int s = off[node], n = deg[node];
    int e = 0;
    for (; e + 2 <= n; e += 2) {
        int ja = __ldg(&ssrc[s + e]);
        int jb = __ldg(&ssrc[s + e + 1]);
        float ra0 = __ldg(&pos[ja * 3 + 0]) + b0;
        float ra1 = __ldg(&pos[ja * 3 + 1]) + b1;
        float ra2 = __ldg(&pos[ja * 3 + 2]) + b2;
        float rb0 = __ldg(&pos[jb * 3 + 0]) + b0;
        float rb1 = __ldg(&pos[jb * 3 + 1]) + b1;
        float rb2 = __ldg(&pos[jb * 3 + 2]) + b2;
        float4 ya = *(const float4*)(y + (size_t)ja * CC + c);
        float4 yb = *(const float4*)(y + (size_t)jb * CC + c);
        acc.x += leaky(ya.x + ra0 * w0.x + ra1 * w1.x + ra2 * w2.x)
               + leaky(yb.x + rb0 * w0.x + rb1 * w1.x + rb2 * w2.x);
        acc.y += leaky(ya.y + ra0 * w0.y + ra1 * w1.y + ra2 * w2.y)
               + leaky(yb.y + rb0 * w0.y + rb1 * w1.y + rb2 * w2.y);
        acc.z += leaky(ya.z + ra0 * w0.z + ra1 * w1.z + ra2 * w2.z)
               + leaky(yb.z + rb0 * w0.z + rb1 * w1.z + rb2 * w2.z);
        acc.w += leaky(ya.w + ra0 * w0.w + ra1 * w1.w + ra2 * w2.w)
               + leaky(yb.w + rb0 * w0.w + rb1 * w1.w + rb2 * w2.w);
    }
    for (; e < n; e++) {
        int j = __ldg(&ssrc[s + e]);
        float r0 = __ldg(&pos[j * 3 + 0]) + b0;
        float r1 = __ldg(&pos[j * 3 + 1]) + b1;
        float r2 = __ldg(&pos[j * 3 + 2]) + b2;
        float4 yv = *(const float4*)(y + (size_t)j * CC + c);
        acc.x += leaky(yv.x + r0 * w0.x + r1 * w1.x + r2 * w2.x);
        acc.y += leaky(yv.y + r0 * w0.y + r1 * w1.y + r2 * w2.y);
        acc.z += leaky(yv.z + r0 * w0.z + r1 * w1.z + r2 * w2.z);
        acc.w += leaky(yv.w + r0 * w0.w + r1 * w1.w + r2 * w2.w);
    }
    *(float4*)(aggr + (size_t)node * CC + c) = acc;
}

// ---------------------------------------------------------------------------
extern "C" void kernel_launch(void* const* d_in, const int* in_sizes, int n_in,
                              void* d_out, int out_size)
{
    const float* x      = (const float*)d_in[0];
    const float* pos    = (const float*)d_in[1];
    const void*  ei     = d_in[2];
    const float* h_w1   = (const float*)d_in[3];
    const float* h_b1   = (const float*)d_in[4];
    const float* h_w2   = (const float*)d_in[5];
    const float* h_b2   = (const float*)d_in[6];
    const float* f_w    = (const float*)d_in[7];
    const float* f_b    = (const float*)d_in[8];
    const float* g_w1   = (const float*)d_in[9];
    const float* g_b1   = (const float*)d_in[10];
    const float* g_w2   = (const float*)d_in[11];
    const float* g_b2   = (const float*)d_in[12];
    float* out = (float*)d_out;

    const int M = in_sizes[0] / CC;  // 50000
    const int E = in_sizes[2] / 2;   // 800000

    float *y, *t, *aggr, *delta;
    int *deg, *off, *cur, *ssrc, *bsum;
    uint4* fragW;
    cudaGetSymbolAddress((void**)&y,     g_y);
    cudaGetSymbolAddress((void**)&t,     g_t);
    cudaGetSymbolAddress((void**)&aggr,  g_aggr);
    cudaGetSymbolAddress((void**)&delta, g_delta);
    cudaGetSymbolAddress((void**)&deg,   g_deg);
    cudaGetSymbolAddress((void**)&off,   g_off);
    cudaGetSymbolAddress((void**)&cur,   g_cur);
    cudaGetSymbolAddress((void**)&ssrc,  g_ssrc);
    cudaGetSymbolAddress((void**)&bsum,  g_bsum);
    cudaGetSymbolAddress((void**)&fragW, g_fragW);

    static int inited = 0;
    static cudaStream_t sB = nullptr, sC = nullptr;
    static cudaEvent_t evFork = nullptr, evJoin = nullptr;
    static cudaEvent_t evPrep = nullptr, evG1 = nullptr;
    if (!inited) {
        cudaFuncSetAttribute(gemm_mma, cudaFuncAttributeMaxDynamicSharedMemorySize, SM_TOT);
        cudaStreamCreateWithFlags(&sB, cudaStreamNonBlocking);
        cudaStreamCreateWithFlags(&sC, cudaStreamNonBlocking);
        cudaEventCreateWithFlags(&evFork, cudaEventDisableTiming);
        cudaEventCreateWithFlags(&evJoin, cudaEventDisableTiming);
        cudaEventCreateWithFlags(&evPrep, cudaEventDisableTiming);
        cudaEventCreateWithFlags(&evG1, cudaEventDisableTiming);
        inited = 1;
    }

    const int gcta = (M + 127) / 128;
    const int ncta = (M + 255) / 256;        // <=256 blocks for M<=65536
    const int e4cta = (E + 1023) / 1024;     // 4 edges/thread

    // --- stream 0: dtype detect (needed by CSR branch) ---
    detect_dtype_kernel<<<1, 256>>>((const int*)ei, 2048);
    cudaEventRecord(evFork, 0);

    // branch B (sB): CSR build (depends only on edge_index + detect)
    cudaStreamWaitEvent(sB, evFork, 0);
    zero_int_kernel<<<ncta, 256, 0, sB>>>(deg, M);
    hist_kernel<<<e4cta, 256, 0, sB>>>(ei, deg, E, M);
    scan1_kernel<<<ncta, 256, 0, sB>>>(deg, off, bsum, M);
    scan2_kernel<<<1, 256, 0, sB>>>(bsum, ncta);
    scan3_kernel<<<ncta, 256, 0, sB>>>(off, cur, bsum, M);
    scatter_kernel<<<e4cta, 256, 0, sB>>>(ei, cur, ssrc, E, M);
    cudaEventRecord(evJoin, sB);

    // stream 0: weight prep, then GEMM2(y); GEMM1(delta) concurrently on sC
    prep_weights_kernel<<<(4 * 4096 + 255) / 256, 256>>>(h_w1, f_w + 3 * CC, g_w1, g_w2);
    cudaEventRecord(evPrep, 0);

    // branch C (sC): delta = tanh(leaky(x @ h_w1 + h_b1) @ h_w2 + h_b2)
    cudaStreamWaitEvent(sC, evPrep, 0);
    gemm_mma<<<gcta, 512, SM_TOT, sC>>>(x, fragW + 0 * 4096, h_b1, nullptr, nullptr, M, 2,
                                        h_w2, h_b2, delta);
    cudaEventRecord(evG1, sC);

    // stream 0: y = x @ f_w[3:, :] + f_b
    gemm_mma<<<gcta, 512, SM_TOT>>>(x, fragW + 1 * 4096, f_b, nullptr, y, M, 0,
                                    nullptr, nullptr, nullptr);

    // --- join: aggregation needs CSR + delta + y ---
    cudaStreamWaitEvent(0, evJoin, 0);
    cudaStreamWaitEvent(0, evG1, 0);
    aggregate_kernel<<<(M * 32 + 255) / 256, 256>>>(off, deg, ssrc, pos, delta, y,
                                                    f_w, aggr, M);

    // t = leaky(aggr @ g_w1 + g_b1)
    gemm_mma<<<gcta, 512, SM_TOT>>>(aggr, fragW + 2 * 4096, g_b1, nullptr, t, M, 1,
                                    nullptr, nullptr, nullptr);
    // out = t @ g_w2 + g_b2 + x
    gemm_mma<<<gcta, 512, SM_TOT>>>(t, fragW + 3 * 4096, g_b2, x, out, M, 0,
                                    nullptr, nullptr, nullptr);
}

// round 15
// speedup vs baseline: 1.4733x; 1.1117x over previous
#include <cuda_runtime.h>
#include <cuda_bf16.h>
#include <cstdint>

#define NN 50000
#define EE 800000
#define CC 128
#define NEG 0.01f

// Scratch (no allocation allowed -> __device__ globals)
__device__ float g_y[NN * CC];
__device__ float g_aggr[NN * CC];
__device__ float g_delta[NN * 3];
__device__ int   g_is64;
// CSR scratch
__device__ int g_deg[NN];
__device__ int g_off[NN];
__device__ int g_cur[NN];
__device__ int g_ssrc[EE];
__device__ int g_bsum[256];
// Fragment-major weights: per matrix 4096 x uint4 {bhi0,bhi1,blo0,blo1} = 64KB
// index (per matrix): ct*256 + kc*32 + g*4 + q
__device__ uint4 g_fragW[4 * 4096];

__device__ __forceinline__ float leaky(float v) {
    return v >= 0.0f ? v : NEG * v;
}

// ---------------------------------------------------------------------------
__global__ void detect_dtype_kernel(const int* __restrict__ ei32, int n_words)
{
    __shared__ int bad;
    if (threadIdx.x == 0) bad = 0;
    __syncthreads();
    int pairs = n_words / 2;
    for (int p = threadIdx.x; p < pairs; p += 256)
        if (ei32[2 * p + 1] != 0) bad = 1;
    __syncthreads();
    if (threadIdx.x == 0) g_is64 = bad ? 0 : 1;
}

// ---------------------------------------------------------------------------
__device__ __forceinline__ uint32_t pack_hi(float a, float b) {
    __nv_bfloat16 ha = __float2bfloat16(a), hb = __float2bfloat16(b);
    return (uint32_t)__bfloat16_as_ushort(ha) | ((uint32_t)__bfloat16_as_ushort(hb) << 16);
}
__device__ __forceinline__ uint32_t pack_lo(float a, float b) {
    __nv_bfloat16 ha = __float2bfloat16(a), hb = __float2bfloat16(b);
    __nv_bfloat16 la = __float2bfloat16(a - __bfloat162float(ha));
    __nv_bfloat16 lb = __float2bfloat16(b - __bfloat162float(hb));
    return (uint32_t)__bfloat16_as_ushort(la) | ((uint32_t)__bfloat16_as_ushort(lb) << 16);
}

__global__ void prep_weights_kernel(const float* __restrict__ w0,
                                    const float* __restrict__ w1,
                                    const float* __restrict__ w2,
                                    const float* __restrict__ w3)
{
    int idx = blockIdx.x * 256 + threadIdx.x;   // 4*4096 entries
    if (idx >= 4 * 4096) return;
    int m = idx >> 12;
    int rem = idx & 4095;
    int col = rem >> 5;        // 0..127
    int kc  = (rem >> 2) & 7;  // 0..7
    int q   = rem & 3;         // 0..3
    const float* w = (m == 0) ? w0 : (m == 1) ? w1 : (m == 2) ? w2 : w3;
    int k0 = kc * 16 + 2 * q;
    float a0 = w[(k0 + 0) * CC + col];
    float a1 = w[(k0 + 1) * CC + col];
    float a2 = w[(k0 + 8) * CC + col];
    float a3 = w[(k0 + 9) * CC + col];
    uint4 v;
    v.x = pack_hi(a0, a1);
    v.y = pack_hi(a2, a3);
    v.z = pack_lo(a0, a1);
    v.w = pack_lo(a2, a3);
    int ct = col >> 3, g = col & 7;
    g_fragW[m * 4096 + ct * 256 + kc * 32 + g * 4 + q] = v;
}

// ---------------------------------------------------------------------------
__device__ __forceinline__ void mma_bf16(float* c, const uint32_t* a, const uint32_t* b)
{
    asm volatile(
        "mma.sync.aligned.m16n8k16.row.col.f32.bf16.bf16.f32 "
        "{%0,%1,%2,%3}, {%4,%5,%6,%7}, {%8,%9}, {%0,%1,%2,%3};"
        : "+f"(c[0]), "+f"(c[1]), "+f"(c[2]), "+f"(c[3])
        : "r"(a[0]), "r"(a[1]), "r"(a[2]), "r"(a[3]), "r"(b[0]), "r"(b[1]));
}

__device__ __forceinline__ void cvt_hilo(float2 f, uint32_t& hi, uint32_t& lo)
{
    __nv_bfloat16 hx = __float2bfloat16(f.x);
    __nv_bfloat16 hy = __float2bfloat16(f.y);
    __nv_bfloat16 lx = __float2bfloat16(f.x - __bfloat162float(hx));
    __nv_bfloat16 ly = __float2bfloat16(f.y - __bfloat162float(hy));
    hi = (uint32_t)__bfloat16_as_ushort(hx) | ((uint32_t)__bfloat16_as_ushort(hy) << 16);
    lo = (uint32_t)__bfloat16_as_ushort(lx) | ((uint32_t)__bfloat16_as_ushort(ly) << 16);
}

// One kc-step of the inner loop given A-fragment source pointers.
__device__ __forceinline__ void inner_step(
    const float* a0p, const float* a1p, int k0,
    const uint4* wbase, int warp_n, float acc[8][4])
{
    float2 f00 = *(const float2*)(a0p + k0);
    float2 f10 = *(const float2*)(a1p + k0);
    float2 f01 = *(const float2*)(a0p + k0 + 8);
    float2 f11 = *(const float2*)(a1p + k0 + 8);
    uint32_t ahi[4], alo[4];
    cvt_hilo(f00, ahi[0], alo[0]);
    cvt_hilo(f10, ahi[1], alo[1]);
    cvt_hilo(f01, ahi[2], alo[2]);
    cvt_hilo(f11, ahi[3], alo[3]);
#pragma unroll
    for (int ct = 0; ct < 8; ct++) {
        uint4 wv = wbase[(warp_n * 8 + ct) * 256];
        uint32_t bh[2] = { wv.x, wv.y };
        uint32_t bl[2] = { wv.z, wv.w };
        mma_bf16(acc[ct], ahi, bh);
        mma_bf16(acc[ct], ahi, bl);
        mma_bf16(acc[ct], alo, bh);
    }
}

// ---------------------------------------------------------------------------
// Split-bf16 GEMM (R10, proven): 512 threads / 16 warps, warp tile 16x64.
// 2 CTAs/SM. act: 0 none(+resid), 1 leaky, 2 delta-fused.
// smem: A [0, 36864); W [36864, 102400); bias [102400,+512); hw2 [102912,+1536)
// ---------------------------------------------------------------------------
#define SM_W    36864
#define SM_BIAS 102400
#define SM_HW2  102912
#define SM_TOT  104448

__global__ __launch_bounds__(512, 2) void gemm_mma(
    const float* __restrict__ A, const uint4* __restrict__ fragW,
    const float* __restrict__ bias, const float* __restrict__ resid,
    float* __restrict__ out, int M, int act,
    const float* __restrict__ hw2, const float* __restrict__ hb2,
    float* __restrict__ delta)
{
    extern __shared__ char sm[];
    float* sA = (float*)sm;                       // [128][72]
    uint4* sW = (uint4*)(sm + SM_W);              // 4096 uint4
    const int tid = threadIdx.x;

#pragma unroll
    for (int i = 0; i < 8; i++)
        sW[tid + i * 512] = fragW[tid + i * 512];
    if (tid < 128) ((float*)(sm + SM_BIAS))[tid] = bias[tid];
    if (act == 2) {
        for (int i = tid; i < 384; i += 512)
            ((float*)(sm + SM_HW2))[i] = hw2[i];
    }

    const int warp = tid >> 5, lane = tid & 31;
    const int g = lane >> 2, q = lane & 3;
    const int warp_m = warp >> 1, warp_n = warp & 1;
    const int r0 = warp_m * 16;

    float acc[8][4];
#pragma unroll
    for (int ct = 0; ct < 8; ct++)
#pragma unroll
        for (int c = 0; c < 4; c++) acc[ct][c] = 0.f;

    const int srow = tid & 127;
    const int sseg = (tid >> 7) * 4;          // float4 seg base 0,4,8,12
    const int grow = blockIdx.x * 128 + srow;
    const float* a0base = sA + (r0 + g) * 72;
    const float* a1base = sA + (r0 + g + 8) * 72;

    for (int half = 0; half < 2; half++) {
        {
            const float4* src = (grow < M)
                ? (const float4*)(A + (size_t)grow * CC + half * 64) : nullptr;
            float* dst = sA + srow * 72;
#pragma unroll
            for (int i = 0; i < 4; i++) {
                float4 v = src ? src[sseg + i] : make_float4(0.f, 0.f, 0.f, 0.f);
                *(float4*)(dst + (sseg + i) * 4) = v;
            }
        }
        __syncthreads();

#pragma unroll
        for (int kc2 = 0; kc2 < 4; kc2++)
            inner_step(a0base, a1base, kc2 * 16 + q * 2,
                       sW + (half * 4 + kc2) * 32 + g * 4 + q, warp_n, acc);
        __syncthreads();
    }

    const float* sbias = (const float*)(sm + SM_BIAS);
    int orow0 = blockIdx.x * 128 + r0 + g;
    int orow1 = orow0 + 8;

    if (act == 2) {
        const float* shw2 = (const float*)(sm + SM_HW2);
        float* sPart = (float*)(sm + SM_W);   // [2][128][3] floats (W dead)
        float p0[3] = {0.f, 0.f, 0.f}, p1[3] = {0.f, 0.f, 0.f};
#pragma unroll
        for (int ct = 0; ct < 8; ct++) {
            int col = (warp_n * 8 + ct) * 8 + q * 2;
            float b0 = sbias[col], b1 = sbias[col + 1];
            float v00 = leaky(acc[ct][0] + b0), v01 = leaky(acc[ct][1] + b1);
            float v10 = leaky(acc[ct][2] + b0), v11 = leaky(acc[ct][3] + b1);
#pragma unroll
            for (int d = 0; d < 3; d++) {
                p0[d] += v00 * shw2[col * 3 + d] + v01 * shw2[(col + 1) * 3 + d];
                p1[d] += v10 * shw2[col * 3 + d] + v11 * shw2[(col + 1) * 3 + d];
            }
        }
#pragma unroll
        for (int d = 0; d < 3; d++) {
            p0[d] += __shfl_xor_sync(0xFFFFFFFFu, p0[d], 1);
            p0[d] += __shfl_xor_sync(0xFFFFFFFFu, p0[d], 2);
            p1[d] += __shfl_xor_sync(0xFFFFFFFFu, p1[d], 1);
            p1[d] += __shfl_xor_sync(0xFFFFFFFFu, p1[d], 2);
        }
        if (q == 0) {
            int row0 = r0 + g, row1 = row0 + 8;
#pragma unroll
            for (int d = 0; d < 3; d++) {
                sPart[(warp_n * 128 + row0) * 3 + d] = p0[d];
                sPart[(warp_n * 128 + row1) * 3 + d] = p1[d];
            }
        }
        __syncthreads();
        if (tid < 128) {
            int orow = blockIdx.x * 128 + tid;
            if (orow < M) {
#pragma unroll
                for (int d = 0; d < 3; d++)
                    delta[orow * 3 + d] = tanhf(sPart[tid * 3 + d] +
                                                sPart[(128 + tid) * 3 + d] + hb2[d]);
            }
        }
        return;
    }

#pragma unroll
    for (int ct = 0; ct < 8; ct++) {
        int col = (warp_n * 8 + ct) * 8 + q * 2;
        float b0 = sbias[col], b1 = sbias[col + 1];
        float v00 = acc[ct][0] + b0, v01 = acc[ct][1] + b1;
        float v10 = acc[ct][2] + b0, v11 = acc[ct][3] + b1;
        if (act == 1) {
            v00 = leaky(v00); v01 = leaky(v01);
            v10 = leaky(v10); v11 = leaky(v11);
        }
        if (orow0 < M) {
            if (resid) {
                float2 r = *(const float2*)(resid + (size_t)orow0 * CC + col);
                v00 += r.x; v01 += r.y;
            }
            *(float2*)(out + (size_t)orow0 * CC + col) = make_float2(v00, v01);
        }
        if (orow1 < M) {
            if (resid) {
                float2 r = *(const float2*)(resid + (size_t)orow1 * CC + col);
                v10 += r.x; v11 += r.y;
            }
            *(float2*)(out + (size_t)orow1 * CC + col) = make_float2(v10, v11);
        }
    }
}

// ---------------------------------------------------------------------------
// Fused GEMM3+GEMM4: out = leaky(aggr@W1 + b1) @ W2 + b2 + x.
// N == K == 128, so each CTA's t-tile fully covers phase-2's K dimension.
// t stays in smem (fp32 [128][132]); 1 CTA/SM.
// smem: stage [0,36864); t [36864,104448); W [104448,169984);
//       b1 [169984,+512); b2 [170496,+512)
// ---------------------------------------------------------------------------
#define F_ST    36864
#define F_SW    104448
#define F_B1    169984
#define F_B2    170496
#define F_TOT   171008

__global__ __launch_bounds__(512, 1) void gemm_fused34(
    const float* __restrict__ A, const uint4* __restrict__ fragW1,
    const uint4* __restrict__ fragW2,
    const float* __restrict__ b1v, const float* __restrict__ b2v,
    const float* __restrict__ resid, float* __restrict__ out, int M)
{
    extern __shared__ char sm[];
    float* sA = (float*)sm;                       // [128][72]
    float* sT = (float*)(sm + F_ST);              // [128][132]
    uint4* sW = (uint4*)(sm + F_SW);              // 4096 uint4
    const int tid = threadIdx.x;

#pragma unroll
    for (int i = 0; i < 8; i++)
        sW[tid + i * 512] = fragW1[tid + i * 512];
    if (tid < 128) {
        ((float*)(sm + F_B1))[tid] = b1v[tid];
        ((float*)(sm + F_B2))[tid] = b2v[tid];
    }

    const int warp = tid >> 5, lane = tid & 31;
    const int g = lane >> 2, q = lane & 3;
    const int warp_m = warp >> 1, warp_n = warp & 1;
    const int r0 = warp_m * 16;

    float acc[8][4];
#pragma unroll
    for (int ct = 0; ct < 8; ct++)
#pragma unroll
        for (int c = 0; c < 4; c++) acc[ct][c] = 0.f;

    const int srow = tid & 127;
    const int sseg = (tid >> 7) * 4;
    const int grow = blockIdx.x * 128 + srow;
    const float* a0base = sA + (r0 + g) * 72;
    const float* a1base = sA + (r0 + g + 8) * 72;

    // ---- phase 1: t = aggr @ W1 ----
    for (int half = 0; half < 2; half++) {
        {
            const float4* src = (grow < M)
                ? (const float4*)(A + (size_t)grow * CC + half * 64) : nullptr;
            float* dst = sA + srow * 72;
#pragma unroll
            for (int i = 0; i < 4; i++) {
                float4 v = src ? src[sseg + i] : make_float4(0.f, 0.f, 0.f, 0.f);
                *(float4*)(dst + (sseg + i) * 4) = v;
            }
        }
        __syncthreads();
#pragma unroll
        for (int kc2 = 0; kc2 < 4; kc2++)
            inner_step(a0base, a1base, kc2 * 16 + q * 2,
                       sW + (half * 4 + kc2) * 32 + g * 4 + q, warp_n, acc);
        __syncthreads();
    }

    // epilogue 1: leaky(acc + b1) -> sT (fp32, stride 132)
    {
        const float* sb1 = (const float*)(sm + F_B1);
        int row0 = r0 + g, row1 = row0 + 8;
#pragma unroll
        for (int ct = 0; ct < 8; ct++) {
            int col = (warp_n * 8 + ct) * 8 + q * 2;
            float b0 = sb1[col], b1 = sb1[col + 1];
            *(float2*)(sT + row0 * 132 + col) =
                make_float2(leaky(acc[ct][0] + b0), leaky(acc[ct][1] + b1));
            *(float2*)(sT + row1 * 132 + col) =
                make_float2(leaky(acc[ct][2] + b0), leaky(acc[ct][3] + b1));
        }
    }
    __syncthreads();

    // swap weights to W2
#pragma unroll
    for (int i = 0; i < 8; i++)
        sW[tid + i * 512] = fragW2[tid + i * 512];
#pragma unroll
    for (int ct = 0; ct < 8; ct++)
#pragma unroll
        for (int c = 0; c < 4; c++) acc[ct][c] = 0.f;
    __syncthreads();

    // ---- phase 2: out = t @ W2 + b2 + x ----
    {
        const float* t0base = sT + (r0 + g) * 132;
        const float* t1base = sT + (r0 + g + 8) * 132;
#pragma unroll
        for (int kc = 0; kc < 8; kc++)
            inner_step(t0base, t1base, kc * 16 + q * 2,
                       sW + kc * 32 + g * 4 + q, warp_n, acc);
    }

    // epilogue 2
    {
        const float* sb2 = (const float*)(sm + F_B2);
        int orow0 = blockIdx.x * 128 + r0 + g;
        int orow1 = orow0 + 8;
#pragma unroll
        for (int ct = 0; ct < 8; ct++) {
            int col = (warp_n * 8 + ct) * 8 + q * 2;
            float b0 = sb2[col], b1 = sb2[col + 1];
            if (orow0 < M) {
                float2 r = *(const float2*)(resid + (size_t)orow0 * CC + col);
                *(float2*)(out + (size_t)orow0 * CC + col) =
                    make_float2(acc[ct][0] + b0 + r.x, acc[ct][1] + b1 + r.y);
            }
            if (orow1 < M) {
                float2 r = *(const float2*)(resid + (size_t)orow1 * CC + col);
                *(float2*)(out + (size_t)orow1 * CC + col) =
                    make_float2(acc[ct][2] + b0 + r.x, acc[ct][3] + b1 + r.y);
            }
        }
    }
}

// ======================= CSR build =========================================
__global__ void zero_int_kernel(int* __restrict__ p, int n)
{
    int i = blockIdx.x * 256 + threadIdx.x;
    if (i < n) p[i] = 0;
}

__global__ void hist_kernel(const void* __restrict__ ei_raw, int* __restrict__ deg,
                            int E, int M)
{
    int base = (blockIdx.x * 256 + threadIdx.x) * 4;
    if (base >= E) return;
    int is64 = g_is64;
    const long long* e64 = (const long long*)ei_raw;
    const int* e32 = (const int*)ei_raw;
    int idx[4];
#pragma unroll
    for (int k = 0; k < 4; k++) {
        int e = base + k;
        idx[k] = (e < E) ? (is64 ? (int)e64[E + e] : e32[E + e]) : -1;
    }
#pragma unroll
    for (int k = 0; k < 4; k++)
        if ((unsigned)idx[k] < (unsigned)M) atomicAdd(&deg[idx[k]], 1);
}

__global__ void scan1_kernel(const int* __restrict__ deg, int* __restrict__ off,
                             int* __restrict__ bsum, int M)
{
    __shared__ int s[256];
    int tid = threadIdx.x;
    int i = blockIdx.x * 256 + tid;
    int d = (i < M) ? deg[i] : 0;
    s[tid] = d;
    __syncthreads();
#pragma unroll
    for (int o = 1; o < 256; o <<= 1) {
        int t = (tid >= o) ? s[tid - o] : 0;
        __syncthreads();
        s[tid] += t;
        __syncthreads();
    }
    if (i < M) off[i] = s[tid] - d;
    if (tid == 255) bsum[blockIdx.x] = s[255];
}

__global__ void scan2_kernel(int* __restrict__ bsum, int nb)
{
    __shared__ int s[256];
    int tid = threadIdx.x;
    int d = (tid < nb) ? bsum[tid] : 0;
    s[tid] = d;
    __syncthreads();
#pragma unroll
    for (int o = 1; o < 256; o <<= 1) {
        int t = (tid >= o) ? s[tid - o] : 0;
        __syncthreads();
        s[tid] += t;
        __syncthreads();
    }
    if (tid < nb) bsum[tid] = s[tid] - d;
}

__global__ void scan3_kernel(int* __restrict__ off, int* __restrict__ cur,
                             const int* __restrict__ bsum, int M)
{
    int i = blockIdx.x * 256 + threadIdx.x;
    if (i >= M) return;
    int v = off[i] + bsum[blockIdx.x];
    off[i] = v;
    cur[i] = v;
}

__global__ void scatter_kernel(const void* __restrict__ ei_raw,
                               int* __restrict__ cur, int* __restrict__ ssrc,
                               int E, int M)
{
    int base = (blockIdx.x * 256 + threadIdx.x) * 4;
    if (base >= E) return;
    int is64 = g_is64;
    const long long* e64 = (const long long*)ei_raw;
    const int* e32 = (const int*)ei_raw;
    int js[4], is_[4];
#pragma unroll
    for (int k = 0; k < 4; k++) {
        int e = base + k;
        if (e < E) {
            js[k]  = is64 ? (int)e64[e]     : e32[e];
            is_[k] = is64 ? (int)e64[E + e] : e32[E + e];
        } else {
            js[k] = -1; is_[k] = -1;
        }
    }
#pragma unroll
    for (int k = 0; k < 4; k++) {
        if ((unsigned)js[k] < (unsigned)M && (unsigned)is_[k] < (unsigned)M) {
            int pos = atomicAdd(&cur[is_[k]], 1);
            ssrc[pos] = js[k];
        }
    }
}

// ---------------------------------------------------------------------------
__global__ __launch_bounds__(256) void aggregate_kernel(
    const int* __restrict__ off, const int* __restrict__ deg,
    const int* __restrict__ ssrc, const float* __restrict__ pos,
    const float* __restrict__ delta, const float* __restrict__ y,
    const float* __restrict__ f_w, float* __restrict__ aggr, int M)
{
    int node = (blockIdx.x * 256 + threadIdx.x) >> 5;
    int lane = threadIdx.x & 31;
    if (node >= M) return;

    int c = lane * 4;
    float4 w0 = *(const float4*)(f_w + 0 * CC + c);
    float4 w1 = *(const float4*)(f_w + 1 * CC + c);
    float4 w2 = *(const float4*)(f_w + 2 * CC + c);
    float b0 = delta[node * 3 + 0] - pos[node * 3 + 0];
    float b1 = delta[node * 3 + 1] - pos[node * 3 + 1];
    float b2 = delta[node * 3 + 2] - pos[node * 3 + 2];

    float4 acc = make_float4(0.f, 0.f, 0.f, 0.f);
    int s = off[node], n = deg[node];
    int e = 0;
    for (; e + 2 <= n; e += 2) {
        int ja = __ldg(&ssrc[s + e]);
        int jb = __ldg(&ssrc[s + e + 1]);
        float ra0 = __ldg(&pos[ja * 3 + 0]) + b0;
        float ra1 = __ldg(&pos[ja * 3 + 1]) + b1;
        float ra2 = __ldg(&pos[ja * 3 + 2]) + b2;
        float rb0 = __ldg(&pos[jb * 3 + 0]) + b0;
        float rb1 = __ldg(&pos[jb * 3 + 1]) + b1;
        float rb2 = __ldg(&pos[jb * 3 + 2]) + b2;
        float4 ya = *(const float4*)(y + (size_t)ja * CC + c);
        float4 yb = *(const float4*)(y + (size_t)jb * CC + c);
        acc.x += leaky(ya.x + ra0 * w0.x + ra1 * w1.x + ra2 * w2.x)
               + leaky(yb.x + rb0 * w0.x + rb1 * w1.x + rb2 * w2.x);
        acc.y += leaky(ya.y + ra0 * w0.y + ra1 * w1.y + ra2 * w2.y)
               + leaky(yb.y + rb0 * w0.y + rb1 * w1.y + rb2 * w2.y);
        acc.z += leaky(ya.z + ra0 * w0.z + ra1 * w1.z + ra2 * w2.z)
               + leaky(yb.z + rb0 * w0.z + rb1 * w1.z + rb2 * w2.z);
        acc.w += leaky(ya.w + ra0 * w0.w + ra1 * w1.w + ra2 * w2.w)
               + leaky(yb.w + rb0 * w0.w + rb1 * w1.w + rb2 * w2.w);
    }
    for (; e < n; e++) {
        int j = __ldg(&ssrc[s + e]);
        float r0 = __ldg(&pos[j * 3 + 0]) + b0;
        float r1 = __ldg(&pos[j * 3 + 1]) + b1;
        float r2 = __ldg(&pos[j * 3 + 2]) + b2;
        float4 yv = *(const float4*)(y + (size_t)j * CC + c);
        acc.x += leaky(yv.x + r0 * w0.x + r1 * w1.x + r2 * w2.x);
        acc.y += leaky(yv.y + r0 * w0.y + r1 * w1.y + r2 * w2.y);
        acc.z += leaky(yv.z + r0 * w0.z + r1 * w1.z + r2 * w2.z);
        acc.w += leaky(yv.w + r0 * w0.w + r1 * w1.w + r2 * w2.w);
    }
    *(float4*)(aggr + (size_t)node * CC + c) = acc;
}

// ---------------------------------------------------------------------------
extern "C" void kernel_launch(void* const* d_in, const int* in_sizes, int n_in,
                              void* d_out, int out_size)
{
    const float* x      = (const float*)d_in[0];
    const float* pos    = (const float*)d_in[1];
    const void*  ei     = d_in[2];
    const float* h_w1   = (const float*)d_in[3];
    const float* h_b1   = (const float*)d_in[4];
    const float* h_w2   = (const float*)d_in[5];
    const float* h_b2   = (const float*)d_in[6];
    const float* f_w    = (const float*)d_in[7];
    const float* f_b    = (const float*)d_in[8];
    const float* g_w1   = (const float*)d_in[9];
    const float* g_b1   = (const float*)d_in[10];
    const float* g_w2   = (const float*)d_in[11];
    const float* g_b2   = (const float*)d_in[12];
    float* out = (float*)d_out;

    const int M = in_sizes[0] / CC;  // 50000
    const int E = in_sizes[2] / 2;   // 800000

    float *y, *aggr, *delta;
    int *deg, *off, *cur, *ssrc, *bsum;
    uint4* fragW;
    cudaGetSymbolAddress((void**)&y,     g_y);
    cudaGetSymbolAddress((void**)&aggr,  g_aggr);
    cudaGetSymbolAddress((void**)&delta, g_delta);
    cudaGetSymbolAddress((void**)&deg,   g_deg);
    cudaGetSymbolAddress((void**)&off,   g_off);
    cudaGetSymbolAddress((void**)&cur,   g_cur);
    cudaGetSymbolAddress((void**)&ssrc,  g_ssrc);
    cudaGetSymbolAddress((void**)&bsum,  g_bsum);
    cudaGetSymbolAddress((void**)&fragW, g_fragW);

    static int inited = 0;
    static cudaStream_t sB = nullptr, sC = nullptr;
    static cudaEvent_t evFork = nullptr, evJoin = nullptr;
    static cudaEvent_t evPrep = nullptr, evG1 = nullptr;
    if (!inited) {
        cudaFuncSetAttribute(gemm_mma, cudaFuncAttributeMaxDynamicSharedMemorySize, SM_TOT);
        cudaFuncSetAttribute(gemm_fused34, cudaFuncAttributeMaxDynamicSharedMemorySize, F_TOT);
        cudaStreamCreateWithFlags(&sB, cudaStreamNonBlocking);
        cudaStreamCreateWithFlags(&sC, cudaStreamNonBlocking);
        cudaEventCreateWithFlags(&evFork, cudaEventDisableTiming);
        cudaEventCreateWithFlags(&evJoin, cudaEventDisableTiming);
        cudaEventCreateWithFlags(&evPrep, cudaEventDisableTiming);
        cudaEventCreateWithFlags(&evG1, cudaEventDisableTiming);
        inited = 1;
    }

    const int gcta = (M + 127) / 128;
    const int ncta = (M + 255) / 256;
    const int e4cta = (E + 1023) / 1024;

    // --- stream 0: dtype detect ---
    detect_dtype_kernel<<<1, 256>>>((const int*)ei, 2048);
    cudaEventRecord(evFork, 0);

    // branch B (sB): CSR build
    cudaStreamWaitEvent(sB, evFork, 0);
    zero_int_kernel<<<ncta, 256, 0, sB>>>(deg, M);
    hist_kernel<<<e4cta, 256, 0, sB>>>(ei, deg, E, M);
    scan1_kernel<<<ncta, 256, 0, sB>>>(deg, off, bsum, M);
    scan2_kernel<<<1, 256, 0, sB>>>(bsum, ncta);
    scan3_kernel<<<ncta, 256, 0, sB>>>(off, cur, bsum, M);
    scatter_kernel<<<e4cta, 256, 0, sB>>>(ei, cur, ssrc, E, M);
    cudaEventRecord(evJoin, sB);

    // stream 0: weight prep; GEMM1 on sC, GEMM2 on 0
    prep_weights_kernel<<<(4 * 4096 + 255) / 256, 256>>>(h_w1, f_w + 3 * CC, g_w1, g_w2);
    cudaEventRecord(evPrep, 0);

    cudaStreamWaitEvent(sC, evPrep, 0);
    gemm_mma<<<gcta, 512, SM_TOT, sC>>>(x, fragW + 0 * 4096, h_b1, nullptr, nullptr, M, 2,
                                        h_w2, h_b2, delta);
    cudaEventRecord(evG1, sC);

    gemm_mma<<<gcta, 512, SM_TOT>>>(x, fragW + 1 * 4096, f_b, nullptr, y, M, 0,
                                    nullptr, nullptr, nullptr);

    // --- join: aggregation needs CSR + delta + y ---
    cudaStreamWaitEvent(0, evJoin, 0);
    cudaStreamWaitEvent(0, evG1, 0);
    aggregate_kernel<<<(M * 32 + 255) / 256, 256>>>(off, deg, ssrc, pos, delta, y,
                                                    f_w, aggr, M);

    // fused: out = leaky(aggr @ g_w1 + g_b1) @ g_w2 + g_b2 + x
    gemm_fused34<<<gcta, 512, F_TOT>>>(aggr, fragW + 2 * 4096, fragW + 3 * 4096,
                                       g_b1, g_b2, x, out, M);
}

// round 16
// speedup vs baseline: 1.5673x; 1.0638x over previous
#include <cuda_runtime.h>
#include <cuda_bf16.h>
#include <cstdint>

#define NN 50000
#define EE 800000
#define CC 128
#define NEG 0.01f

// Scratch (no allocation allowed -> __device__ globals)
__device__ float g_y[NN * CC];
__device__ float g_aggr[NN * CC];
__device__ float g_delta[NN * 3];
__device__ int   g_is64;
// CSR scratch
__device__ int g_deg[NN];
__device__ int g_off[NN];
__device__ int g_cur[NN];
__device__ int g_ssrc[EE];
__device__ int g_bsum[256];
// Fragment-major weights: per matrix 4096 x uint4 {bhi0,bhi1,blo0,blo1} = 64KB
// index (per matrix): ct*256 + kc*32 + g*4 + q
__device__ uint4 g_fragW[4 * 4096];

__device__ __forceinline__ float leaky(float v) {
    return v >= 0.0f ? v : NEG * v;
}

// ---------------------------------------------------------------------------
__global__ void detect_dtype_kernel(const int* __restrict__ ei32, int n_words)
{
    __shared__ int bad;
    if (threadIdx.x == 0) bad = 0;
    __syncthreads();
    int pairs = n_words / 2;
    for (int p = threadIdx.x; p < pairs; p += 256)
        if (ei32[2 * p + 1] != 0) bad = 1;
    __syncthreads();
    if (threadIdx.x == 0) g_is64 = bad ? 0 : 1;
}

// ---------------------------------------------------------------------------
__device__ __forceinline__ uint32_t pack_hi(float a, float b) {
    __nv_bfloat16 ha = __float2bfloat16(a), hb = __float2bfloat16(b);
    return (uint32_t)__bfloat16_as_ushort(ha) | ((uint32_t)__bfloat16_as_ushort(hb) << 16);
}
__device__ __forceinline__ uint32_t pack_lo(float a, float b) {
    __nv_bfloat16 ha = __float2bfloat16(a), hb = __float2bfloat16(b);
    __nv_bfloat16 la = __float2bfloat16(a - __bfloat162float(ha));
    __nv_bfloat16 lb = __float2bfloat16(b - __bfloat162float(hb));
    return (uint32_t)__bfloat16_as_ushort(la) | ((uint32_t)__bfloat16_as_ushort(lb) << 16);
}

__global__ void prep_weights_kernel(const float* __restrict__ w0,
                                    const float* __restrict__ w1,
                                    const float* __restrict__ w2,
                                    const float* __restrict__ w3)
{
    int idx = blockIdx.x * 256 + threadIdx.x;   // 4*4096 entries
    if (idx >= 4 * 4096) return;
    int m = idx >> 12;
    int rem = idx & 4095;
    int col = rem >> 5;        // 0..127
    int kc  = (rem >> 2) & 7;  // 0..7
    int q   = rem & 3;         // 0..3
    const float* w = (m == 0) ? w0 : (m == 1) ? w1 : (m == 2) ? w2 : w3;
    int k0 = kc * 16 + 2 * q;
    float a0 = w[(k0 + 0) * CC + col];
    float a1 = w[(k0 + 1) * CC + col];
    float a2 = w[(k0 + 8) * CC + col];
    float a3 = w[(k0 + 9) * CC + col];
    uint4 v;
    v.x = pack_hi(a0, a1);
    v.y = pack_hi(a2, a3);
    v.z = pack_lo(a0, a1);
    v.w = pack_lo(a2, a3);
    int ct = col >> 3, g = col & 7;
    g_fragW[m * 4096 + ct * 256 + kc * 32 + g * 4 + q] = v;
}

// ---------------------------------------------------------------------------
__device__ __forceinline__ void mma_bf16(float* c, const uint32_t* a, const uint32_t* b)
{
    asm volatile(
        "mma.sync.aligned.m16n8k16.row.col.f32.bf16.bf16.f32 "
        "{%0,%1,%2,%3}, {%4,%5,%6,%7}, {%8,%9}, {%0,%1,%2,%3};"
        : "+f"(c[0]), "+f"(c[1]), "+f"(c[2]), "+f"(c[3])
        : "r"(a[0]), "r"(a[1]), "r"(a[2]), "r"(a[3]), "r"(b[0]), "r"(b[1]));
}

__device__ __forceinline__ void cvt_hilo(float2 f, uint32_t& hi, uint32_t& lo)
{
    __nv_bfloat16 hx = __float2bfloat16(f.x);
    __nv_bfloat16 hy = __float2bfloat16(f.y);
    __nv_bfloat16 lx = __float2bfloat16(f.x - __bfloat162float(hx));
    __nv_bfloat16 ly = __float2bfloat16(f.y - __bfloat162float(hy));
    hi = (uint32_t)__bfloat16_as_ushort(hx) | ((uint32_t)__bfloat16_as_ushort(hy) << 16);
    lo = (uint32_t)__bfloat16_as_ushort(lx) | ((uint32_t)__bfloat16_as_ushort(ly) << 16);
}

// One kc-step of the inner loop given A-fragment source pointers.
__device__ __forceinline__ void inner_step(
    const float* a0p, const float* a1p, int k0,
    const uint4* wbase, int warp_n, float acc[8][4])
{
    float2 f00 = *(const float2*)(a0p + k0);
    float2 f10 = *(const float2*)(a1p + k0);
    float2 f01 = *(const float2*)(a0p + k0 + 8);
    float2 f11 = *(const float2*)(a1p + k0 + 8);
    uint32_t ahi[4], alo[4];
    cvt_hilo(f00, ahi[0], alo[0]);
    cvt_hilo(f10, ahi[1], alo[1]);
    cvt_hilo(f01, ahi[2], alo[2]);
    cvt_hilo(f11, ahi[3], alo[3]);
#pragma unroll
    for (int ct = 0; ct < 8; ct++) {
        uint4 wv = wbase[(warp_n * 8 + ct) * 256];
        uint32_t bh[2] = { wv.x, wv.y };
        uint32_t bl[2] = { wv.z, wv.w };
        mma_bf16(acc[ct], ahi, bh);
        mma_bf16(acc[ct], ahi, bl);
        mma_bf16(acc[ct], alo, bh);
    }
}

// ---------------------------------------------------------------------------
// Fused GEMM1+GEMM2: x staged once (stride 136 f32, conflict-free).
// Phase 1 (W=h_w1): delta = tanh(leaky(x@h_w1+h_b1) @ h_w2 + h_b2).
// Phase 2 (W=f_w'): y = x @ f_w[3:] + f_b   (no activation).
// smem: x [0,69632); W [69632,135168); b1 +512; b2 +512; hw2 +1536.
// ---------------------------------------------------------------------------
#define F12_SW   69632
#define F12_B1   135168
#define F12_B2   135680
#define F12_HW2  136192
#define F12_TOT  137728

__global__ __launch_bounds__(512, 1) void gemm_fused12(
    const float* __restrict__ x,
    const uint4* __restrict__ fragW1, const uint4* __restrict__ fragW2,
    const float* __restrict__ b1v, const float* __restrict__ b2v,
    const float* __restrict__ hw2, const float* __restrict__ hb2,
    float* __restrict__ delta, float* __restrict__ yout, int M)
{
    extern __shared__ char sm[];
    float* sX = (float*)sm;                       // [128][136]
    uint4* sW = (uint4*)(sm + F12_SW);            // 4096 uint4
    const int tid = threadIdx.x;

#pragma unroll
    for (int i = 0; i < 8; i++)
        sW[tid + i * 512] = fragW1[tid + i * 512];
    if (tid < 128) {
        ((float*)(sm + F12_B1))[tid] = b1v[tid];
        ((float*)(sm + F12_B2))[tid] = b2v[tid];
    }
    for (int i = tid; i < 384; i += 512)
        ((float*)(sm + F12_HW2))[i] = hw2[i];

    // Stage full x tile [128 x 128] fp32, row stride 136
    {
        int srow = tid & 127;
        int segb = (tid >> 7) * 8;                // 8 float4 segs of 32
        int grow = blockIdx.x * 128 + srow;
        const float4* src = (grow < M) ? (const float4*)(x + (size_t)grow * CC) : nullptr;
        float* dst = sX + srow * 136;
#pragma unroll
        for (int i = 0; i < 8; i++) {
            float4 v = src ? src[segb + i] : make_float4(0.f, 0.f, 0.f, 0.f);
            *(float4*)(dst + (segb + i) * 4) = v;
        }
    }
    __syncthreads();

    const int warp = tid >> 5, lane = tid & 31;
    const int g = lane >> 2, q = lane & 3;
    const int warp_m = warp >> 1, warp_n = warp & 1;
    const int r0 = warp_m * 16;
    const float* a0base = sX + (r0 + g) * 136;
    const float* a1base = sX + (r0 + g + 8) * 136;

    float acc[8][4];
#pragma unroll
    for (int ct = 0; ct < 8; ct++)
#pragma unroll
        for (int c = 0; c < 4; c++) acc[ct][c] = 0.f;

    // ---- phase 1: hidden = x @ h_w1 ----
#pragma unroll
    for (int kc = 0; kc < 8; kc++)
        inner_step(a0base, a1base, kc * 16 + q * 2,
                   sW + kc * 32 + g * 4 + q, warp_n, acc);
    __syncthreads();   // all warps done reading sW before sPart aliases it

    // delta epilogue: leaky(acc+b1) @ hw2, quad-reduce, cross-warp_n via smem
    {
        const float* sb1 = (const float*)(sm + F12_B1);
        const float* shw2 = (const float*)(sm + F12_HW2);
        float* sPart = (float*)(sm + F12_SW);     // [2][128][3] (W1 dead)
        float p0[3] = {0.f, 0.f, 0.f}, p1[3] = {0.f, 0.f, 0.f};
#pragma unroll
        for (int ct = 0; ct < 8; ct++) {
            int col = (warp_n * 8 + ct) * 8 + q * 2;
            float b0 = sb1[col], b1 = sb1[col + 1];
            float v00 = leaky(acc[ct][0] + b0), v01 = leaky(acc[ct][1] + b1);
            float v10 = leaky(acc[ct][2] + b0), v11 = leaky(acc[ct][3] + b1);
#pragma unroll
            for (int d = 0; d < 3; d++) {
                p0[d] += v00 * shw2[col * 3 + d] + v01 * shw2[(col + 1) * 3 + d];
                p1[d] += v10 * shw2[col * 3 + d] + v11 * shw2[(col + 1) * 3 + d];
            }
        }
#pragma unroll
        for (int d = 0; d < 3; d++) {
            p0[d] += __shfl_xor_sync(0xFFFFFFFFu, p0[d], 1);
            p0[d] += __shfl_xor_sync(0xFFFFFFFFu, p0[d], 2);
            p1[d] += __shfl_xor_sync(0xFFFFFFFFu, p1[d], 1);
            p1[d] += __shfl_xor_sync(0xFFFFFFFFu, p1[d], 2);
        }
        if (q == 0) {
            int row0 = r0 + g, row1 = row0 + 8;
#pragma unroll
            for (int d = 0; d < 3; d++) {
                sPart[(warp_n * 128 + row0) * 3 + d] = p0[d];
                sPart[(warp_n * 128 + row1) * 3 + d] = p1[d];
            }
        }
        __syncthreads();
        if (tid < 128) {
            int orow = blockIdx.x * 128 + tid;
            if (orow < M) {
#pragma unroll
                for (int d = 0; d < 3; d++)
                    delta[orow * 3 + d] = tanhf(sPart[tid * 3 + d] +
                                                sPart[(128 + tid) * 3 + d] + hb2[d]);
            }
        }
    }
    __syncthreads();

    // swap weights to W2 (f_w'), zero accumulators
#pragma unroll
    for (int i = 0; i < 8; i++)
        sW[tid + i * 512] = fragW2[tid + i * 512];
#pragma unroll
    for (int ct = 0; ct < 8; ct++)
#pragma unroll
        for (int c = 0; c < 4; c++) acc[ct][c] = 0.f;
    __syncthreads();

    // ---- phase 2: y = x @ f_w' + f_b ----
#pragma unroll
    for (int kc = 0; kc < 8; kc++)
        inner_step(a0base, a1base, kc * 16 + q * 2,
                   sW + kc * 32 + g * 4 + q, warp_n, acc);

    {
        const float* sb2 = (const float*)(sm + F12_B2);
        int orow0 = blockIdx.x * 128 + r0 + g;
        int orow1 = orow0 + 8;
#pragma unroll
        for (int ct = 0; ct < 8; ct++) {
            int col = (warp_n * 8 + ct) * 8 + q * 2;
            float b0 = sb2[col], b1 = sb2[col + 1];
            if (orow0 < M)
                *(float2*)(yout + (size_t)orow0 * CC + col) =
                    make_float2(acc[ct][0] + b0, acc[ct][1] + b1);
            if (orow1 < M)
                *(float2*)(yout + (size_t)orow1 * CC + col) =
                    make_float2(acc[ct][2] + b0, acc[ct][3] + b1);
        }
    }
}

// ---------------------------------------------------------------------------
// Fused GEMM3+GEMM4 (R15, proven): out = leaky(aggr@W1 + b1) @ W2 + b2 + x.
// smem: stage [0,36864); t [36864,104448); W [104448,169984); b1 +512; b2 +512
// ---------------------------------------------------------------------------
#define F_ST    36864
#define F_SW    104448
#define F_B1    169984
#define F_B2    170496
#define F_TOT   171008

__global__ __launch_bounds__(512, 1) void gemm_fused34(
    const float* __restrict__ A, const uint4* __restrict__ fragW1,
    const uint4* __restrict__ fragW2,
    const float* __restrict__ b1v, const float* __restrict__ b2v,
    const float* __restrict__ resid, float* __restrict__ out, int M)
{
    extern __shared__ char sm[];
    float* sA = (float*)sm;                       // [128][72]
    float* sT = (float*)(sm + F_ST);              // [128][132]
    uint4* sW = (uint4*)(sm + F_SW);              // 4096 uint4
    const int tid = threadIdx.x;

#pragma unroll
    for (int i = 0; i < 8; i++)
        sW[tid + i * 512] = fragW1[tid + i * 512];
    if (tid < 128) {
        ((float*)(sm + F_B1))[tid] = b1v[tid];
        ((float*)(sm + F_B2))[tid] = b2v[tid];
    }

    const int warp = tid >> 5, lane = tid & 31;
    const int g = lane >> 2, q = lane & 3;
    const int warp_m = warp >> 1, warp_n = warp & 1;
    const int r0 = warp_m * 16;

    float acc[8][4];
#pragma unroll
    for (int ct = 0; ct < 8; ct++)
#pragma unroll
        for (int c = 0; c < 4; c++) acc[ct][c] = 0.f;

    const int srow = tid & 127;
    const int sseg = (tid >> 7) * 4;
    const int grow = blockIdx.x * 128 + srow;
    const float* a0base = sA + (r0 + g) * 72;
    const float* a1base = sA + (r0 + g + 8) * 72;

    for (int half = 0; half < 2; half++) {
        {
            const float4* src = (grow < M)
                ? (const float4*)(A + (size_t)grow * CC + half * 64) : nullptr;
            float* dst = sA + srow * 72;
#pragma unroll
            for (int i = 0; i < 4; i++) {
                float4 v = src ? src[sseg + i] : make_float4(0.f, 0.f, 0.f, 0.f);
                *(float4*)(dst + (sseg + i) * 4) = v;
            }
        }
        __syncthreads();
#pragma unroll
        for (int kc2 = 0; kc2 < 4; kc2++)
            inner_step(a0base, a1base, kc2 * 16 + q * 2,
                       sW + (half * 4 + kc2) * 32 + g * 4 + q, warp_n, acc);
        __syncthreads();
    }

    {
        const float* sb1 = (const float*)(sm + F_B1);
        int row0 = r0 + g, row1 = row0 + 8;
#pragma unroll
        for (int ct = 0; ct < 8; ct++) {
            int col = (warp_n * 8 + ct) * 8 + q * 2;
            float b0 = sb1[col], b1 = sb1[col + 1];
            *(float2*)(sT + row0 * 132 + col) =
                make_float2(leaky(acc[ct][0] + b0), leaky(acc[ct][1] + b1));
            *(float2*)(sT + row1 * 132 + col) =
                make_float2(leaky(acc[ct][2] + b0), leaky(acc[ct][3] + b1));
        }
    }
    __syncthreads();

#pragma unroll
    for (int i = 0; i < 8; i++)
        sW[tid + i * 512] = fragW2[tid + i * 512];
#pragma unroll
    for (int ct = 0; ct < 8; ct++)
#pragma unroll
        for (int c = 0; c < 4; c++) acc[ct][c] = 0.f;
    __syncthreads();

    {
        const float* t0base = sT + (r0 + g) * 132;
        const float* t1base = sT + (r0 + g + 8) * 132;
#pragma unroll
        for (int kc = 0; kc < 8; kc++)
            inner_step(t0base, t1base, kc * 16 + q * 2,
                       sW + kc * 32 + g * 4 + q, warp_n, acc);
    }

    {
        const float* sb2 = (const float*)(sm + F_B2);
        int orow0 = blockIdx.x * 128 + r0 + g;
        int orow1 = orow0 + 8;
#pragma unroll
        for (int ct = 0; ct < 8; ct++) {
            int col = (warp_n * 8 + ct) * 8 + q * 2;
            float b0 = sb2[col], b1 = sb2[col + 1];
            if (orow0 < M) {
                float2 r = *(const float2*)(resid + (size_t)orow0 * CC + col);
                *(float2*)(out + (size_t)orow0 * CC + col) =
                    make_float2(acc[ct][0] + b0 + r.x, acc[ct][1] + b1 + r.y);
            }
            if (orow1 < M) {
                float2 r = *(const float2*)(resid + (size_t)orow1 * CC + col);
                *(float2*)(out + (size_t)orow1 * CC + col) =
                    make_float2(acc[ct][2] + b0 + r.x, acc[ct][3] + b1 + r.y);
            }
        }
    }
}

// ======================= CSR build =========================================
__global__ void zero_int_kernel(int* __restrict__ p, int n)
{
    int i = blockIdx.x * 256 + threadIdx.x;
    if (i < n) p[i] = 0;
}

__global__ void hist_kernel(const void* __restrict__ ei_raw, int* __restrict__ deg,
                            int E, int M)
{
    int base = (blockIdx.x * 256 + threadIdx.x) * 4;
    if (base >= E) return;
    int is64 = g_is64;
    const long long* e64 = (const long long*)ei_raw;
    const int* e32 = (const int*)ei_raw;
    int idx[4];
#pragma unroll
    for (int k = 0; k < 4; k++) {
        int e = base + k;
        idx[k] = (e < E) ? (is64 ? (int)e64[E + e] : e32[E + e]) : -1;
    }
#pragma unroll
    for (int k = 0; k < 4; k++)
        if ((unsigned)idx[k] < (unsigned)M) atomicAdd(&deg[idx[k]], 1);
}

__global__ void scan1_kernel(const int* __restrict__ deg, int* __restrict__ off,
                             int* __restrict__ bsum, int M)
{
    __shared__ int s[256];
    int tid = threadIdx.x;
    int i = blockIdx.x * 256 + tid;
    int d = (i < M) ? deg[i] : 0;
    s[tid] = d;
    __syncthreads();
#pragma unroll
    for (int o = 1; o < 256; o <<= 1) {
        int t = (tid >= o) ? s[tid - o] : 0;
        __syncthreads();
        s[tid] += t;
        __syncthreads();
    }
    if (i < M) off[i] = s[tid] - d;
    if (tid == 255) bsum[blockIdx.x] = s[255];
}

__global__ void scan2_kernel(int* __restrict__ bsum, int nb)
{
    __shared__ int s[256];
    int tid = threadIdx.x;
    int d = (tid < nb) ? bsum[tid] : 0;
    s[tid] = d;
    __syncthreads();
#pragma unroll
    for (int o = 1; o < 256; o <<= 1) {
        int t = (tid >= o) ? s[tid - o] : 0;
        __syncthreads();
        s[tid] += t;
        __syncthreads();
    }
    if (tid < nb) bsum[tid] = s[tid] - d;
}

__global__ void scan3_kernel(int* __restrict__ off, int* __restrict__ cur,
                             const int* __restrict__ bsum, int M)
{
    int i = blockIdx.x * 256 + threadIdx.x;
    if (i >= M) return;
    int v = off[i] + bsum[blockIdx.x];
    off[i] = v;
    cur[i] = v;
}

__global__ void scatter_kernel(const void* __restrict__ ei_raw,
                               int* __restrict__ cur, int* __restrict__ ssrc,
                               int E, int M)
{
    int base = (blockIdx.x * 256 + threadIdx.x) * 4;
    if (base >= E) return;
    int is64 = g_is64;
    const long long* e64 = (const long long*)ei_raw;
    const int* e32 = (const int*)ei_raw;
    int js[4], is_[4];
#pragma unroll
    for (int k = 0; k < 4; k++) {
        int e = base + k;
        if (e < E) {
            js[k]  = is64 ? (int)e64[e]     : e32[e];
            is_[k] = is64 ? (int)e64[E + e] : e32[E + e];
        } else {
            js[k] = -1; is_[k] = -1;
        }
    }
#pragma unroll
    for (int k = 0; k < 4; k++) {
        if ((unsigned)js[k] < (unsigned)M && (unsigned)is_[k] < (unsigned)M) {
            int pos = atomicAdd(&cur[is_[k]], 1);
            ssrc[pos] = js[k];
        }
    }
}

// ---------------------------------------------------------------------------
__global__ __launch_bounds__(256) void aggregate_kernel(
    const int* __restrict__ off, const int* __restrict__ deg,
    const int* __restrict__ ssrc, const float* __restrict__ pos,
    const float* __restrict__ delta, const float* __restrict__ y,
    const float* __restrict__ f_w, float* __restrict__ aggr, int M)
{
    int node = (blockIdx.x * 256 + threadIdx.x) >> 5;
    int lane = threadIdx.x & 31;
    if (node >= M) return;

    int c = lane * 4;
    float4 w0 = *(const float4*)(f_w + 0 * CC + c);
    float4 w1 = *(const float4*)(f_w + 1 * CC + c);
    float4 w2 = *(const float4*)(f_w + 2 * CC + c);
    float b0 = delta[node * 3 + 0] - pos[node * 3 + 0];
    float b1 = delta[node * 3 + 1] - pos[node * 3 + 1];
    float b2 = delta[node * 3 + 2] - pos[node * 3 + 2];

    float4 acc = make_float4(0.f, 0.f, 0.f, 0.f);
    int s = off[node], n = deg[node];
    int e = 0;
    for (; e + 2 <= n; e += 2) {
        int ja = __ldg(&ssrc[s + e]);
        int jb = __ldg(&ssrc[s + e + 1]);
        float ra0 = __ldg(&pos[ja * 3 + 0]) + b0;
        float ra1 = __ldg(&pos[ja * 3 + 1]) + b1;
        float ra2 = __ldg(&pos[ja * 3 + 2]) + b2;
        float rb0 = __ldg(&pos[jb * 3 + 0]) + b0;
        float rb1 = __ldg(&pos[jb * 3 + 1]) + b1;
        float rb2 = __ldg(&pos[jb * 3 + 2]) + b2;
        float4 ya = *(const float4*)(y + (size_t)ja * CC + c);
        float4 yb = *(const float4*)(y + (size_t)jb * CC + c);
        acc.x += leaky(ya.x + ra0 * w0.x + ra1 * w1.x + ra2 * w2.x)
               + leaky(yb.x + rb0 * w0.x + rb1 * w1.x + rb2 * w2.x);
        acc.y += leaky(ya.y + ra0 * w0.y + ra1 * w1.y + ra2 * w2.y)
               + leaky(yb.y + rb0 * w0.y + rb1 * w1.y + rb2 * w2.y);
        acc.z += leaky(ya.z + ra0 * w0.z + ra1 * w1.z + ra2 * w2.z)
               + leaky(yb.z + rb0 * w0.z + rb1 * w1.z + rb2 * w2.z);
        acc.w += leaky(ya.w + ra0 * w0.w + ra1 * w1.w + ra2 * w2.w)
               + leaky(yb.w + rb0 * w0.w + rb1 * w1.w + rb2 * w2.w);
    }
    for (; e < n; e++) {
        int j = __ldg(&ssrc[s + e]);
        float r0 = __ldg(&pos[j * 3 + 0]) + b0;
        float r1 = __ldg(&pos[j * 3 + 1]) + b1;
        float r2 = __ldg(&pos[j * 3 + 2]) + b2;
        float4 yv = *(const float4*)(y + (size_t)j * CC + c);
        acc.x += leaky(yv.x + r0 * w0.x + r1 * w1.x + r2 * w2.x);
        acc.y += leaky(yv.y + r0 * w0.y + r1 * w1.y + r2 * w2.y);
        acc.z += leaky(yv.z + r0 * w0.z + r1 * w1.z + r2 * w2.z);
        acc.w += leaky(yv.w + r0 * w0.w + r1 * w1.w + r2 * w2.w);
    }
    *(float4*)(aggr + (size_t)node * CC + c) = acc;
}

// ---------------------------------------------------------------------------
extern "C" void kernel_launch(void* const* d_in, const int* in_sizes, int n_in,
                              void* d_out, int out_size)
{
    const float* x      = (const float*)d_in[0];
    const float* pos    = (const float*)d_in[1];
    const void*  ei     = d_in[2];
    const float* h_w1   = (const float*)d_in[3];
    const float* h_b1   = (const float*)d_in[4];
    const float* h_w2   = (const float*)d_in[5];
    const float* h_b2   = (const float*)d_in[6];
    const float* f_w    = (const float*)d_in[7];
    const float* f_b    = (const float*)d_in[8];
    const float* g_w1   = (const float*)d_in[9];
    const float* g_b1   = (const float*)d_in[10];
    const float* g_w2   = (const float*)d_in[11];
    const float* g_b2   = (const float*)d_in[12];
    float* out = (float*)d_out;

    const int M = in_sizes[0] / CC;  // 50000
    const int E = in_sizes[2] / 2;   // 800000

    float *y, *aggr, *delta;
    int *deg, *off, *cur, *ssrc, *bsum;
    uint4* fragW;
    cudaGetSymbolAddress((void**)&y,     g_y);
    cudaGetSymbolAddress((void**)&aggr,  g_aggr);
    cudaGetSymbolAddress((void**)&delta, g_delta);
    cudaGetSymbolAddress((void**)&deg,   g_deg);
    cudaGetSymbolAddress((void**)&off,   g_off);
    cudaGetSymbolAddress((void**)&cur,   g_cur);
    cudaGetSymbolAddress((void**)&ssrc,  g_ssrc);
    cudaGetSymbolAddress((void**)&bsum,  g_bsum);
    cudaGetSymbolAddress((void**)&fragW, g_fragW);

    static int inited = 0;
    static cudaStream_t sB = nullptr;
    static cudaEvent_t evFork = nullptr, evJoin = nullptr;
    if (!inited) {
        cudaFuncSetAttribute(gemm_fused12, cudaFuncAttributeMaxDynamicSharedMemorySize, F12_TOT);
        cudaFuncSetAttribute(gemm_fused34, cudaFuncAttributeMaxDynamicSharedMemorySize, F_TOT);
        cudaStreamCreateWithFlags(&sB, cudaStreamNonBlocking);
        cudaEventCreateWithFlags(&evFork, cudaEventDisableTiming);
        cudaEventCreateWithFlags(&evJoin, cudaEventDisableTiming);
        inited = 1;
    }

    const int gcta = (M + 127) / 128;
    const int ncta = (M + 255) / 256;
    const int e4cta = (E + 1023) / 1024;

    // --- stream 0: dtype detect ---
    detect_dtype_kernel<<<1, 256>>>((const int*)ei, 2048);
    cudaEventRecord(evFork, 0);

    // branch B (sB): CSR build (hidden under fused12)
    cudaStreamWaitEvent(sB, evFork, 0);
    zero_int_kernel<<<ncta, 256, 0, sB>>>(deg, M);
    hist_kernel<<<e4cta, 256, 0, sB>>>(ei, deg, E, M);
    scan1_kernel<<<ncta, 256, 0, sB>>>(deg, off, bsum, M);
    scan2_kernel<<<1, 256, 0, sB>>>(bsum, ncta);
    scan3_kernel<<<ncta, 256, 0, sB>>>(off, cur, bsum, M);
    scatter_kernel<<<e4cta, 256, 0, sB>>>(ei, cur, ssrc, E, M);
    cudaEventRecord(evJoin, sB);

    // stream 0: weight prep + fused GEMM1+GEMM2
    prep_weights_kernel<<<(4 * 4096 + 255) / 256, 256>>>(h_w1, f_w + 3 * CC, g_w1, g_w2);
    gemm_fused12<<<gcta, 512, F12_TOT>>>(x, fragW + 0 * 4096, fragW + 1 * 4096,
                                         h_b1, f_b, h_w2, h_b2, delta, y, M);

    // --- join: aggregation needs CSR + delta + y ---
    cudaStreamWaitEvent(0, evJoin, 0);
    aggregate_kernel<<<(M * 32 + 255) / 256, 256>>>(off, deg, ssrc, pos, delta, y,
                                                    f_w, aggr, M);

    // fused: out = leaky(aggr @ g_w1 + g_b1) @ g_w2 + g_b2 + x
    gemm_fused34<<<gcta, 512, F_TOT>>>(aggr, fragW + 2 * 4096, fragW + 3 * 4096,
                                       g_b1, g_b2, x, out, M);
}